// round 13
// baseline (speedup 1.0000x reference)
#include <cuda_runtime.h>
#include <cuda_bf16.h>
#include <math.h>
#include <stdint.h>

#define B_   4
#define S_   2048
#define D_   1024
#define H_   16
#define HD_  64
#define E_   8
#define F_   4096
#define FS_  2048
#define T_   (B_*S_)
#define CAP_ 2560
#define NKT  (2*T_)
#define TD   ((size_t)T_*D_)

// fp32 scratch
__device__ float g_x1  [T_*D_];
__device__ float g_xn2 [T_*D_];
__device__ float g_sh2 [T_*D_];
__device__ float g_eo  [(size_t)E_*CAP_*D_];
__device__ float g_bqkv[3*D_];
__device__ int   g_eidx[NKT];
__device__ int   g_pos [NKT];
__device__ float g_gate[NKT];
// bf16 split planes
__device__ __nv_bfloat16 g_qkvp [9*(size_t)T_*D_];   // [z(q,k,v)][plane 0..2][T][D]
__device__ __nv_bfloat16 g_xn1p [3*(size_t)T_*D_];
__device__ __nv_bfloat16 g_attnp[3*(size_t)T_*D_];
__device__ __nv_bfloat16 g_xn2p [2*(size_t)T_*D_];
__device__ __nv_bfloat16 g_dispp[2*(size_t)E_*CAP_*D_];
__device__ __nv_bfloat16 g_hbufp[2*(size_t)E_*CAP_*F_];
__device__ __nv_bfloat16 g_sh1p [2*(size_t)T_*FS_];

#define MEG (1024ULL*1024ULL)
#define OFF_Q  0ULL
#define OFF_Kw (3ULL*MEG)
#define OFF_V  (6ULL*MEG)
#define OFF_O  (9ULL*MEG)
#define OFF_S1 (12ULL*MEG)
#define OFF_S2 (16ULL*MEG)
#define OFF_W1 (20ULL*MEG)
#define OFF_W2 (84ULL*MEG)
#define WT_TOT (148ULL*MEG)
__device__ __nv_bfloat16 g_wt[WT_TOT];

__device__ __forceinline__ float gelu_exact(float v) {
    return 0.5f * v * (1.0f + erff(v * 0.7071067811865476f));
}
__device__ __forceinline__ uint32_t s2u(const void* p) {
    uint32_t a;
    asm("{ .reg .u64 t; cvta.to.shared.u64 t, %1; cvt.u32.u64 %0, t; }" : "=r"(a) : "l"(p));
    return a;
}
__device__ __forceinline__ uint32_t pk2(__nv_bfloat16 a, __nv_bfloat16 b) {
    return (uint32_t)__bfloat16_as_ushort(a) | ((uint32_t)__bfloat16_as_ushort(b) << 16);
}
__device__ __forceinline__ void mma16816(float* d, const uint32_t* a, const uint32_t* b) {
    asm volatile("mma.sync.aligned.m16n8k16.row.col.f32.bf16.bf16.f32 "
        "{%0,%1,%2,%3}, {%4,%5,%6,%7}, {%8,%9}, {%0,%1,%2,%3};"
        : "+f"(d[0]), "+f"(d[1]), "+f"(d[2]), "+f"(d[3])
        : "r"(a[0]), "r"(a[1]), "r"(a[2]), "r"(a[3]), "r"(b[0]), "r"(b[1]));
}
#define LDSM_X4(r, addr) \
    asm volatile("ldmatrix.sync.aligned.m8n8.x4.shared.b16 {%0,%1,%2,%3}, [%4];" \
        : "=r"((r)[0]), "=r"((r)[1]), "=r"((r)[2]), "=r"((r)[3]) : "r"(addr))
#define LDSM_X4T(r, addr) \
    asm volatile("ldmatrix.sync.aligned.m8n8.x4.trans.shared.b16 {%0,%1,%2,%3}, [%4];" \
        : "=r"((r)[0]), "=r"((r)[1]), "=r"((r)[2]), "=r"((r)[3]) : "r"(addr))
#define CP16(smaddr, gptr) \
    asm volatile("cp.async.cg.shared.global [%0], [%1], 16;" :: "r"(smaddr), "l"(gptr))
#define CP_COMMIT() asm volatile("cp.async.commit_group;" ::: "memory")
#define CP_WAIT0()  asm volatile("cp.async.wait_group 0;" ::: "memory")

// ===== weight transpose + split: W[K,N] -> Wt[s][n][k], 64k x 32n tiles, uint4 stores =====
template<int NS>
__global__ void wtrans_kernel(const float* __restrict__ W, __nv_bfloat16* __restrict__ Wt,
                              int K, int N)
{
    __shared__ float t[64][33];
    const long long wb = (long long)blockIdx.z * K * N;
    __nv_bfloat16* out = Wt + (long long)blockIdx.z * NS * (long long)K * N;
    const long long plane = (long long)K * N;
    const int n0 = blockIdx.x * 32, k0 = blockIdx.y * 64;
    #pragma unroll
    for (int jj = 0; jj < 8; jj++)
        t[threadIdx.y + 8 * jj][threadIdx.x] =
            W[wb + (long long)(k0 + threadIdx.y + 8 * jj) * N + n0 + threadIdx.x];
    __syncthreads();
    const int tid = threadIdx.y * 32 + threadIdx.x;
    const int n_loc = tid >> 3, k8 = (tid & 7) * 8;
    float v[8];
    #pragma unroll
    for (int e = 0; e < 8; e++) v[e] = t[k8 + e][n_loc];
    const long long o = (long long)(n0 + n_loc) * K + k0 + k8;
    #pragma unroll
    for (int s = 0; s < NS; s++) {
        __nv_bfloat16 h[8];
        #pragma unroll
        for (int e = 0; e < 8; e++) {
            h[e] = __float2bfloat16(v[e]);
            if (s + 1 < NS) v[e] -= __bfloat162float(h[e]);
        }
        uint4 pkv;
        pkv.x = pk2(h[0], h[1]); pkv.y = pk2(h[2], h[3]);
        pkv.z = pk2(h[4], h[5]); pkv.w = pk2(h[6], h[7]);
        *(uint4*)(out + s * plane + o) = pkv;
    }
}

// ===== HMMA GEMM: both operands pre-split bf16 planes, full cp.async =====
// OUT: 0 = fp32, 1 = fp32+residual, 2 = gelu + split2 bf16, 3 = split3 bf16 (scale 0.125 on z==0)
#define RS 40
#define PLB (128*RS*2)

template<int NS, int OUT>
__global__ __launch_bounds__(256, (NS == 2) ? 2 : 1)
void hmma_gemm_kernel(const __nv_bfloat16* __restrict__ Ap, const __nv_bfloat16* __restrict__ Bt,
                      const float* __restrict__ bias, const float* __restrict__ Rsrc,
                      float* __restrict__ Cf, __nv_bfloat16* __restrict__ Cp,
                      int N, int K,
                      long long planeA, long long sAb, long long sBb, long long sBias,
                      long long sCb, long long planeC)
{
    extern __shared__ __align__(16) char sm[];
    const int tid = threadIdx.x, wid = tid >> 5, lane = tid & 31;
    const int STG = 2 * NS * PLB;

    Ap   += (long long)blockIdx.z * sAb;
    Bt   += (long long)blockIdx.z * sBb;
    bias += (long long)blockIdx.z * sBias;
    if (OUT >= 2) Cp += (long long)blockIdx.z * sCb;
    else          Cf += (long long)blockIdx.z * sCb;
    if (OUT == 1) Rsrc += (long long)blockIdx.z * sCb;

    const long long planeB = (long long)N * K;
    const int rowBase = blockIdx.y * 128, colBase = blockIdx.x * 128;
    const uint32_t smb = s2u(sm);

    const int lr = tid >> 1, kh = (tid & 1) * 16;
    const __nv_bfloat16* aRow = Ap + (long long)(rowBase + lr) * K + kh;
    const __nv_bfloat16* bRow = Bt + (long long)(colBase + lr) * K + kh;
    const uint32_t aOff = (uint32_t)(lr * (RS * 2) + kh * 2);
    const uint32_t bOff = (uint32_t)(NS * PLB + lr * (RS * 2) + kh * 2);

    const int wm = (wid & 3) * 32, wn = (wid >> 2) * 64;
    const uint32_t aFragO = (uint32_t)((wm + (lane & 15)) * (RS * 2) + ((lane >> 4) * 8) * 2);
    const uint32_t bFragO = (uint32_t)(NS * PLB
        + (wn + (lane >> 4) * 8 + (lane & 7)) * (RS * 2) + ((lane >> 3) & 1) * 16);

    float acc[2][8][4];
    #pragma unroll
    for (int mi = 0; mi < 2; mi++)
        #pragma unroll
        for (int ni = 0; ni < 8; ni++)
            #pragma unroll
            for (int c = 0; c < 4; c++) acc[mi][ni][c] = 0.f;

    const int nIter = K >> 5;

    #pragma unroll
    for (int s = 0; s < NS; s++) {
        CP16(smb + s * PLB + aOff,      aRow + s * planeA);
        CP16(smb + s * PLB + aOff + 16, aRow + s * planeA + 8);
        CP16(smb + s * PLB + bOff,      bRow + s * planeB);
        CP16(smb + s * PLB + bOff + 16, bRow + s * planeB + 8);
    }
    CP_COMMIT();

    for (int it = 0; it < nIter; ++it) {
        const uint32_t sb = smb + (uint32_t)(it & 1) * STG;
        CP_WAIT0();
        __syncthreads();

        if (it + 1 < nIter) {
            const int kn = (it + 1) << 5;
            const uint32_t sn = smb + (uint32_t)((it + 1) & 1) * STG;
            #pragma unroll
            for (int s = 0; s < NS; s++) {
                CP16(sn + s * PLB + aOff,      aRow + s * planeA + kn);
                CP16(sn + s * PLB + aOff + 16, aRow + s * planeA + kn + 8);
                CP16(sn + s * PLB + bOff,      bRow + s * planeB + kn);
                CP16(sn + s * PLB + bOff + 16, bRow + s * planeB + kn + 8);
            }
            CP_COMMIT();
        }

        #pragma unroll
        for (int kk = 0; kk < 32; kk += 16) {
            uint32_t af[NS][2][4];
            #pragma unroll
            for (int i = 0; i < NS; i++)
                #pragma unroll
                for (int mi = 0; mi < 2; mi++)
                    LDSM_X4(af[i][mi], sb + i * PLB + aFragO + (mi * 16) * (RS * 2) + kk * 2);
            #pragma unroll
            for (int j = 0; j < NS; j++) {
                uint32_t bfr[16];
                #pragma unroll
                for (int p = 0; p < 4; p++)
                    LDSM_X4(bfr + p * 4, sb + j * PLB + bFragO + (p * 16) * (RS * 2) + kk * 2);
                #pragma unroll
                for (int i = 0; i < NS; i++) {
                    if (i + j >= NS) continue;
                    #pragma unroll
                    for (int mi = 0; mi < 2; mi++)
                        #pragma unroll
                        for (int ni = 0; ni < 8; ni++)
                            mma16816(acc[mi][ni], af[i][mi],
                                     bfr + (ni >> 1) * 4 + (ni & 1) * 2);
                }
            }
        }
        __syncthreads();
    }

    const float sc = (OUT == 3 && blockIdx.z == 0) ? 0.125f : 1.0f;
    #pragma unroll
    for (int mi = 0; mi < 2; mi++) {
        #pragma unroll
        for (int half = 0; half < 2; half++) {
            const int r = rowBase + wm + mi * 16 + (lane >> 2) + half * 8;
            const long long cidx = (long long)r * N + colBase + wn + (lane & 3) * 2;
            const float* bp = bias + colBase + wn + (lane & 3) * 2;
            #pragma unroll
            for (int ni = 0; ni < 8; ni++) {
                float x0 = acc[mi][ni][half * 2 + 0] + bp[ni * 8];
                float x1 = acc[mi][ni][half * 2 + 1] + bp[ni * 8 + 1];
                if (OUT == 2) {
                    x0 = gelu_exact(x0); x1 = gelu_exact(x1);
                    __nv_bfloat16 h0 = __float2bfloat16(x0), h1 = __float2bfloat16(x1);
                    __nv_bfloat16 l0 = __float2bfloat16(x0 - __bfloat162float(h0));
                    __nv_bfloat16 l1 = __float2bfloat16(x1 - __bfloat162float(h1));
                    *(uint32_t*)(Cp + cidx + ni * 8)          = pk2(h0, h1);
                    *(uint32_t*)(Cp + planeC + cidx + ni * 8) = pk2(l0, l1);
                } else if (OUT == 3) {
                    x0 *= sc; x1 *= sc;
                    #pragma unroll
                    for (int pl = 0; pl < 3; pl++) {
                        __nv_bfloat16 h0 = __float2bfloat16(x0), h1 = __float2bfloat16(x1);
                        if (pl < 2) {
                            x0 -= __bfloat162float(h0);
                            x1 -= __bfloat162float(h1);
                        }
                        *(uint32_t*)(Cp + pl * planeC + cidx + ni * 8) = pk2(h0, h1);
                    }
                } else {
                    if (OUT == 1) {
                        float2 rr = *(const float2*)(Rsrc + cidx + ni * 8);
                        x0 += rr.x; x1 += rr.y;
                    }
                    float2 o2; o2.x = x0; o2.y = x1;
                    *(float2*)(Cf + cidx + ni * 8) = o2;
                }
            }
        }
    }
}

// ===== HMMA flash attention v2: pre-split bf16 plane inputs, cp.async K/V pipeline =====
#define ARS 72
#define QPL (128*ARS*2)
#define KPL (64*ARS*2)
#define ATTN_SM (3*QPL + 2*6*KPL)

__global__ __launch_bounds__(256)
void attn_hmma_kernel(const __nv_bfloat16* __restrict__ Qp, const __nv_bfloat16* __restrict__ Kp,
                      const __nv_bfloat16* __restrict__ Vp, const unsigned char* __restrict__ mask,
                      __nv_bfloat16* __restrict__ Op)
{
    extern __shared__ __align__(16) char smr[];
    const int tid = threadIdx.x, wid = tid >> 5, lane = tid & 31;
    const int h = blockIdx.y, b = blockIdx.z;
    const size_t qrow0 = (size_t)b * S_ + blockIdx.x * 128;
    const uint32_t uQ = s2u(smr);
    const uint32_t uKV = uQ + 3 * QPL;

    // load Q planes (pre-scaled, pre-split by QKV GEMM epilogue)
    #pragma unroll
    for (int i = 0; i < 12; i++) {
        const int c = i * 256 + tid;
        const int pl = c >> 10, rem = c & 1023;
        const int row = rem >> 3, ch = rem & 7;
        const __nv_bfloat16* src = Qp + (size_t)pl * TD + (qrow0 + row) * D_ + h * HD_ + ch * 8;
        *(uint4*)(smr + pl * QPL + row * (ARS * 2) + ch * 16) = *(const uint4*)src;
    }

    // K/V tile fill helper values
    const int fc_tensor = (tid * 12) >= 0 ? 0 : 0; // (placeholder, real mapping below)

    float o[8][4];
    #pragma unroll
    for (int nf = 0; nf < 8; nf++)
        #pragma unroll
        for (int c = 0; c < 4; c++) o[nf][c] = 0.f;
    float mrun0 = -1e30f, mrun1 = -1e30f, l0 = 0.f, l1 = 0.f;
    const int grp = lane >> 3;

    // prologue fill j=0 -> stage 0
    {
        const size_t rb = (size_t)(b * S_) * D_ + h * HD_;
        #pragma unroll
        for (int i = 0; i < 12; i++) {
            const int c = i * 256 + tid;
            const int tensor = c / 1536, rem = c % 1536;
            const int pl = rem / 512, rem2 = rem % 512;
            const int row = rem2 >> 3, ch = rem2 & 7;
            const __nv_bfloat16* base = tensor ? Vp : Kp;
            const __nv_bfloat16* src = base + (size_t)pl * TD + rb + (size_t)row * D_ + ch * 8;
            CP16(uKV + (tensor * 3 + pl) * KPL + row * (ARS * 2) + ch * 16, src);
        }
        CP_COMMIT();
    }
    __syncthreads();   // Q planes visible

    for (int j = 0; j < S_ / 64; j++) {
        const uint32_t uKs = uKV + (uint32_t)(j & 1) * (6 * KPL);
        const uint32_t uVs = uKs + 3 * KPL;
        CP_WAIT0();
        __syncthreads();

        if (j + 1 < S_ / 64) {
            const uint32_t un = uKV + (uint32_t)((j + 1) & 1) * (6 * KPL);
            const size_t rb = (size_t)(b * S_ + (j + 1) * 64) * D_ + h * HD_;
            #pragma unroll
            for (int i = 0; i < 12; i++) {
                const int c = i * 256 + tid;
                const int tensor = c / 1536, rem = c % 1536;
                const int pl = rem / 512, rem2 = rem % 512;
                const int row = rem2 >> 3, ch = rem2 & 7;
                const __nv_bfloat16* base = tensor ? Vp : Kp;
                const __nv_bfloat16* src = base + (size_t)pl * TD + rb + (size_t)row * D_ + ch * 8;
                CP16(un + (tensor * 3 + pl) * KPL + row * (ARS * 2) + ch * 16, src);
            }
            CP_COMMIT();
        }

        // ---- S = Q K^T ----
        float sacc[8][4];
        #pragma unroll
        for (int nf = 0; nf < 8; nf++)
            #pragma unroll
            for (int c = 0; c < 4; c++) sacc[nf][c] = 0.f;

        #pragma unroll
        for (int jpl = 0; jpl < 3; jpl++) {
            #pragma unroll
            for (int kf = 0; kf < 4; kf++) {
                uint32_t kb[16];
                #pragma unroll
                for (int nfp = 0; nfp < 4; nfp++) {
                    uint32_t addr = uKs + jpl * KPL
                        + (uint32_t)((nfp * 16 + (grp >> 1) * 8 + (lane & 7)) * (ARS * 2))
                        + kf * 32 + (grp & 1) * 16;
                    LDSM_X4(kb + nfp * 4, addr);
                }
                #pragma unroll
                for (int ipl = 0; ipl < 3; ipl++) {
                    if (ipl + jpl >= 3) continue;
                    uint32_t aq[4];
                    uint32_t qaddr = uQ + ipl * QPL
                        + (uint32_t)((wid * 16 + (lane & 15)) * (ARS * 2))
                        + kf * 32 + (lane >> 4) * 16;
                    LDSM_X4(aq, qaddr);
                    #pragma unroll
                    for (int nf = 0; nf < 8; nf++)
                        mma16816(sacc[nf], aq, kb + (nf >> 1) * 4 + (nf & 1) * 2);
                }
            }
        }

        // ---- mask + online softmax ----
        const unsigned char* mrow = mask + b * S_ + j * 64;
        #pragma unroll
        for (int nf = 0; nf < 8; nf++) {
            uchar2 mm = *(const uchar2*)(mrow + nf * 8 + (lane & 3) * 2);
            if (mm.x) { sacc[nf][0] = -1e30f; sacc[nf][2] = -1e30f; }
            if (mm.y) { sacc[nf][1] = -1e30f; sacc[nf][3] = -1e30f; }
        }
        float nm0 = mrun0, nm1 = mrun1;
        #pragma unroll
        for (int nf = 0; nf < 8; nf++) {
            nm0 = fmaxf(nm0, fmaxf(sacc[nf][0], sacc[nf][1]));
            nm1 = fmaxf(nm1, fmaxf(sacc[nf][2], sacc[nf][3]));
        }
        nm0 = fmaxf(nm0, __shfl_xor_sync(0xffffffffu, nm0, 1));
        nm0 = fmaxf(nm0, __shfl_xor_sync(0xffffffffu, nm0, 2));
        nm1 = fmaxf(nm1, __shfl_xor_sync(0xffffffffu, nm1, 1));
        nm1 = fmaxf(nm1, __shfl_xor_sync(0xffffffffu, nm1, 2));
        const float al0 = __expf(mrun0 - nm0), al1 = __expf(mrun1 - nm1);
        mrun0 = nm0; mrun1 = nm1;
        float ps0 = 0.f, ps1 = 0.f;
        #pragma unroll
        for (int nf = 0; nf < 8; nf++) {
            sacc[nf][0] = __expf(sacc[nf][0] - nm0); ps0 += sacc[nf][0];
            sacc[nf][1] = __expf(sacc[nf][1] - nm0); ps0 += sacc[nf][1];
            sacc[nf][2] = __expf(sacc[nf][2] - nm1); ps1 += sacc[nf][2];
            sacc[nf][3] = __expf(sacc[nf][3] - nm1); ps1 += sacc[nf][3];
        }
        ps0 += __shfl_xor_sync(0xffffffffu, ps0, 1);
        ps0 += __shfl_xor_sync(0xffffffffu, ps0, 2);
        ps1 += __shfl_xor_sync(0xffffffffu, ps1, 1);
        ps1 += __shfl_xor_sync(0xffffffffu, ps1, 2);
        l0 = l0 * al0 + ps0;
        l1 = l1 * al1 + ps1;
        #pragma unroll
        for (int nf = 0; nf < 8; nf++) {
            o[nf][0] *= al0; o[nf][1] *= al0; o[nf][2] *= al1; o[nf][3] *= al1;
        }

        // ---- P 3-split A fragments ----
        uint32_t pa[3][4][4];
        #pragma unroll
        for (int kf = 0; kf < 4; kf++) {
            float e[8];
            e[0] = sacc[2*kf][0];   e[1] = sacc[2*kf][1];
            e[2] = sacc[2*kf][2];   e[3] = sacc[2*kf][3];
            e[4] = sacc[2*kf+1][0]; e[5] = sacc[2*kf+1][1];
            e[6] = sacc[2*kf+1][2]; e[7] = sacc[2*kf+1][3];
            #pragma unroll
            for (int pl = 0; pl < 3; pl++) {
                __nv_bfloat16 hh[8];
                #pragma unroll
                for (int q = 0; q < 8; q++) {
                    hh[q] = __float2bfloat16(e[q]);
                    if (pl < 2) e[q] -= __bfloat162float(hh[q]);
                }
                pa[pl][kf][0] = pk2(hh[0], hh[1]);
                pa[pl][kf][1] = pk2(hh[2], hh[3]);
                pa[pl][kf][2] = pk2(hh[4], hh[5]);
                pa[pl][kf][3] = pk2(hh[6], hh[7]);
            }
        }

        // ---- O += P V ----
        #pragma unroll
        for (int vpl = 0; vpl < 3; vpl++) {
            #pragma unroll
            for (int kf = 0; kf < 4; kf++) {
                uint32_t vb[16];
                #pragma unroll
                for (int nfp = 0; nfp < 4; nfp++) {
                    uint32_t addr = uVs + vpl * KPL
                        + (uint32_t)((kf * 16 + (grp & 1) * 8 + (lane & 7)) * (ARS * 2))
                        + (2 * nfp + (grp >> 1)) * 16;
                    LDSM_X4T(vb + nfp * 4, addr);
                }
                #pragma unroll
                for (int ppl = 0; ppl < 3; ppl++) {
                    if (ppl + vpl >= 3) continue;
                    #pragma unroll
                    for (int nf = 0; nf < 8; nf++)
                        mma16816(o[nf], pa[ppl][kf], vb + (nf >> 1) * 4 + (nf & 1) * 2);
                }
            }
        }
    }

    const float inv0 = (l0 > 0.f) ? 1.f / l0 : 0.f;
    const float inv1 = (l1 > 0.f) ? 1.f / l1 : 0.f;
    const size_t row0 = qrow0 + wid * 16 + (lane >> 2);
    const size_t idx0 = row0 * D_ + h * HD_ + (lane & 3) * 2;
    const size_t idx1 = idx0 + 8 * D_;
    #pragma unroll
    for (int nf = 0; nf < 8; nf++) {
        float vx = o[nf][0] * inv0, vy = o[nf][1] * inv0;
        float wx = o[nf][2] * inv1, wy = o[nf][3] * inv1;
        #pragma unroll
        for (int pl = 0; pl < 3; pl++) {
            __nv_bfloat16 hx = __float2bfloat16(vx), hy = __float2bfloat16(vy);
            __nv_bfloat16 gx = __float2bfloat16(wx), gy = __float2bfloat16(wy);
            if (pl < 2) {
                vx -= __bfloat162float(hx); vy -= __bfloat162float(hy);
                wx -= __bfloat162float(gx); wy -= __bfloat162float(gy);
            }
            *(uint32_t*)(Op + pl * TD + idx0 + nf * 8) = pk2(hx, hy);
            *(uint32_t*)(Op + pl * TD + idx1 + nf * 8) = pk2(gx, gy);
        }
    }
}

// ===== LayerNorm -> bf16 planes (+ optional fp32) =====
template<int NS, bool F32>
__global__ void ln_kernel(const float* __restrict__ x, const float* __restrict__ g,
                          const float* __restrict__ b, float* __restrict__ outf,
                          __nv_bfloat16* __restrict__ outp)
{
    const int t = blockIdx.x, tid = threadIdx.x;
    const float* xr = x + (size_t)t * D_;
    const int i0 = tid * 4;
    float4 xv = *(const float4*)(xr + i0);
    float s  = xv.x + xv.y + xv.z + xv.w;
    float s2 = xv.x * xv.x + xv.y * xv.y + xv.z * xv.z + xv.w * xv.w;
    __shared__ float sm1[8], sm2[8];
    #pragma unroll
    for (int o = 16; o > 0; o >>= 1) {
        s  += __shfl_down_sync(0xffffffffu, s,  o);
        s2 += __shfl_down_sync(0xffffffffu, s2, o);
    }
    const int wid = tid >> 5, lane = tid & 31;
    if (lane == 0) { sm1[wid] = s; sm2[wid] = s2; }
    __syncthreads();
    if (tid == 0) {
        float a = 0.f, c = 0.f;
        #pragma unroll
        for (int w = 0; w < 8; w++) { a += sm1[w]; c += sm2[w]; }
        sm1[0] = a; sm2[0] = c;
    }
    __syncthreads();
    const float mean = sm1[0] * (1.f / D_);
    const float var  = sm2[0] * (1.f / D_) - mean * mean;
    const float rstd = rsqrtf(var + 1e-5f);
    float4 gv = *(const float4*)(g + i0);
    float4 bv = *(const float4*)(b + i0);
    float y[4];
    y[0] = (xv.x - mean) * rstd * gv.x + bv.x;
    y[1] = (xv.y - mean) * rstd * gv.y + bv.y;
    y[2] = (xv.z - mean) * rstd * gv.z + bv.z;
    y[3] = (xv.w - mean) * rstd * gv.w + bv.w;
    if (F32) *(float4*)(outf + (size_t)t * D_ + i0) = *(float4*)y;
    float v[4] = {y[0], y[1], y[2], y[3]};
    #pragma unroll
    for (int sp = 0; sp < NS; sp++) {
        __nv_bfloat16 h[4];
        #pragma unroll
        for (int e = 0; e < 4; e++) {
            h[e] = __float2bfloat16(v[e]);
            if (sp + 1 < NS) v[e] -= __bfloat162float(h[e]);
        }
        uint2 pkv; pkv.x = pk2(h[0], h[1]); pkv.y = pk2(h[2], h[3]);
        *(uint2*)(outp + (size_t)sp * TD + (size_t)t * D_ + i0) = pkv;
    }
}

// ===== router =====
__global__ void router_kernel(const float* __restrict__ xn, const float* __restrict__ wr,
                              int* __restrict__ eidx, float* __restrict__ gate)
{
    const int t = blockIdx.x;
    float acc[E_];
    #pragma unroll
    for (int e = 0; e < E_; e++) acc[e] = 0.f;
    const float* xr = xn + (size_t)t * D_;
    for (int i = threadIdx.x; i < D_; i += 256) {
        const float xv = xr[i];
        const float* wrow = wr + (size_t)i * E_;
        #pragma unroll
        for (int e = 0; e < E_; e++) acc[e] += xv * wrow[e];
    }
    __shared__ float red[8][E_];
    #pragma unroll
    for (int e = 0; e < E_; e++)
        #pragma unroll
        for (int o = 16; o > 0; o >>= 1)
            acc[e] += __shfl_down_sync(0xffffffffu, acc[e], o);
    const int wid = threadIdx.x >> 5, lane = threadIdx.x & 31;
    if (lane == 0)
        #pragma unroll
        for (int e = 0; e < E_; e++) red[wid][e] = acc[e];
    __syncthreads();
    if (threadIdx.x == 0) {
        float lg[E_];
        #pragma unroll
        for (int e = 0; e < E_; e++) {
            float s = 0.f;
            #pragma unroll
            for (int w = 0; w < 8; w++) s += red[w][e];
            lg[e] = s;
        }
        float m = lg[0];
        #pragma unroll
        for (int e = 1; e < E_; e++) m = fmaxf(m, lg[e]);
        float p[E_], sum = 0.f;
        #pragma unroll
        for (int e = 0; e < E_; e++) { p[e] = expf(lg[e] - m); sum += p[e]; }
        const float invs = 1.f / sum;
        #pragma unroll
        for (int e = 0; e < E_; e++) p[e] *= invs;
        int e0 = 0;
        #pragma unroll
        for (int e = 1; e < E_; e++) if (p[e] > p[e0]) e0 = e;
        int e1 = (e0 == 0) ? 1 : 0;
        #pragma unroll
        for (int e = 0; e < E_; e++) if (e != e0 && p[e] > p[e1]) e1 = e;
        const float v0 = p[e0], v1 = p[e1];
        const float inv = 1.f / (v0 + v1);
        eidx[t]      = e0; gate[t]      = v0 * inv;
        eidx[T_ + t] = e1; gate[T_ + t] = v1 * inv;
    }
}

__global__ void pos_kernel(const int* __restrict__ eidx, int* __restrict__ pos)
{
    const int e = blockIdx.x;
    __shared__ int cnts[256];
    const int base = threadIdx.x * 64;
    int c = 0;
    for (int i = 0; i < 64; i++) c += (eidx[base + i] == e) ? 1 : 0;
    cnts[threadIdx.x] = c;
    __syncthreads();
    if (threadIdx.x == 0) {
        int run = 0;
        for (int k = 0; k < 256; k++) { int v = cnts[k]; cnts[k] = run; run += v; }
    }
    __syncthreads();
    int run = cnts[threadIdx.x];
    for (int i = 0; i < 64; i++)
        if (eidx[base + i] == e) pos[base + i] = run++;
}

__global__ void scatter_kernel(const __nv_bfloat16* __restrict__ xp, const int* __restrict__ eidx,
                               const int* __restrict__ pos, __nv_bfloat16* __restrict__ dp)
{
    const int i = blockIdx.x;
    const int p = pos[i];
    if (p >= CAP_) return;
    const int e = eidx[i];
    const int t = i & (T_ - 1);
    const size_t PL = (size_t)E_ * CAP_ * D_;
    #pragma unroll
    for (int pl = 0; pl < 2; pl++) {
        const uint2* src = (const uint2*)(xp + (size_t)pl * TD + (size_t)t * D_);
        uint2* dst = (uint2*)(dp + pl * PL + ((size_t)e * CAP_ + p) * D_);
        dst[threadIdx.x] = src[threadIdx.x];
    }
}

__global__ void combine_kernel(const float* __restrict__ x1, const float* __restrict__ sh2,
                               const float* __restrict__ eo, const int* __restrict__ eidx,
                               const int* __restrict__ pos, const float* __restrict__ gate,
                               float* __restrict__ out)
{
    const int t = blockIdx.x;
    const int i0 = t, i1 = T_ + t;
    const int p0 = pos[i0], p1 = pos[i1];
    const float w0 = (p0 < CAP_) ? gate[i0] : 0.f;
    const float w1 = (p1 < CAP_) ? gate[i1] : 0.f;
    const float* e0p = eo + ((size_t)eidx[i0] * CAP_ + min(p0, CAP_ - 1)) * D_;
    const float* e1p = eo + ((size_t)eidx[i1] * CAP_ + min(p1, CAP_ - 1)) * D_;
    const size_t off = (size_t)t * D_;
    for (int d = threadIdx.x; d < D_; d += 256)
        out[off + d] = x1[off + d] + sh2[off + d] + w0 * e0p[d] + w1 * e1p[d];
}

// ===== host =====
template<int NS, int OUT>
static void hgemm(const __nv_bfloat16* Ap, const __nv_bfloat16* Bt, const float* bias,
                  const float* R, float* Cf, __nv_bfloat16* Cp,
                  int M, int N, int K, int batch,
                  long long planeA, long long sAb, long long sBb, long long sBias,
                  long long sCb, long long planeC)
{
    const int smem = 4 * NS * PLB;
    static bool init[2][4] = {};
    if (!init[NS - 2][OUT]) {
        cudaFuncSetAttribute(hmma_gemm_kernel<NS, OUT>,
                             cudaFuncAttributeMaxDynamicSharedMemorySize, smem);
        init[NS - 2][OUT] = true;
    }
    dim3 grid(N / 128, M / 128, batch);
    hmma_gemm_kernel<NS, OUT><<<grid, 256, smem>>>(Ap, Bt, bias, R, Cf, Cp, N, K,
                                                   planeA, sAb, sBb, sBias, sCb, planeC);
}

extern "C" void kernel_launch(void* const* d_in, const int* in_sizes, int n_in,
                              void* d_out, int out_size)
{
    const float* x      = (const float*)d_in[0];
    const unsigned char* mask = (const unsigned char*)d_in[1];
    const float* ln1_g  = (const float*)d_in[2];
    const float* ln1_b  = (const float*)d_in[3];
    const float* wq     = (const float*)d_in[4];
    const float* bq     = (const float*)d_in[5];
    const float* wk     = (const float*)d_in[6];
    const float* bk     = (const float*)d_in[7];
    const float* wv     = (const float*)d_in[8];
    const float* bv     = (const float*)d_in[9];
    const float* wo     = (const float*)d_in[10];
    const float* bo     = (const float*)d_in[11];
    const float* ln2_g  = (const float*)d_in[12];
    const float* ln2_b  = (const float*)d_in[13];
    const float* wrout  = (const float*)d_in[14];
    const float* w1     = (const float*)d_in[15];
    const float* b1     = (const float*)d_in[16];
    const float* w2     = (const float*)d_in[17];
    const float* b2     = (const float*)d_in[18];
    const float* ws1    = (const float*)d_in[19];
    const float* bs1    = (const float*)d_in[20];
    const float* ws2    = (const float*)d_in[21];
    const float* bs2    = (const float*)d_in[22];
    float* out = (float*)d_out;

    float *x1, *xn2, *sh2, *eo, *gate, *bqkv;
    int *eidx, *pos;
    __nv_bfloat16 *wt, *qkvp, *xn1p, *attnp, *xn2p, *dispp, *hbufp, *sh1p;
    cudaGetSymbolAddress((void**)&x1,    g_x1);
    cudaGetSymbolAddress((void**)&xn2,   g_xn2);
    cudaGetSymbolAddress((void**)&sh2,   g_sh2);
    cudaGetSymbolAddress((void**)&eo,    g_eo);
    cudaGetSymbolAddress((void**)&gate,  g_gate);
    cudaGetSymbolAddress((void**)&bqkv,  g_bqkv);
    cudaGetSymbolAddress((void**)&eidx,  g_eidx);
    cudaGetSymbolAddress((void**)&pos,   g_pos);
    cudaGetSymbolAddress((void**)&wt,    g_wt);
    cudaGetSymbolAddress((void**)&qkvp,  g_qkvp);
    cudaGetSymbolAddress((void**)&xn1p,  g_xn1p);
    cudaGetSymbolAddress((void**)&attnp, g_attnp);
    cudaGetSymbolAddress((void**)&xn2p,  g_xn2p);
    cudaGetSymbolAddress((void**)&dispp, g_dispp);
    cudaGetSymbolAddress((void**)&hbufp, g_hbufp);
    cudaGetSymbolAddress((void**)&sh1p,  g_sh1p);

    static bool ainit = false;
    if (!ainit) {
        cudaFuncSetAttribute(attn_hmma_kernel, cudaFuncAttributeMaxDynamicSharedMemorySize, ATTN_SM);
        ainit = true;
    }

    cudaMemcpyAsync(bqkv,          bq, D_ * sizeof(float), cudaMemcpyDeviceToDevice, 0);
    cudaMemcpyAsync(bqkv + D_,     bk, D_ * sizeof(float), cudaMemcpyDeviceToDevice, 0);
    cudaMemcpyAsync(bqkv + 2 * D_, bv, D_ * sizeof(float), cudaMemcpyDeviceToDevice, 0);

    // ---- weight transpose + split (64k x 32n tiles) ----
    dim3 tb(32, 8);
    wtrans_kernel<3><<<dim3(32, 16, 1), tb>>>(wq,  wt + OFF_Q,  D_, D_);
    wtrans_kernel<3><<<dim3(32, 16, 1), tb>>>(wk,  wt + OFF_Kw, D_, D_);
    wtrans_kernel<3><<<dim3(32, 16, 1), tb>>>(wv,  wt + OFF_V,  D_, D_);
    wtrans_kernel<3><<<dim3(32, 16, 1), tb>>>(wo,  wt + OFF_O,  D_, D_);
    wtrans_kernel<2><<<dim3(64, 16, 1), tb>>>(ws1, wt + OFF_S1, D_, FS_);
    wtrans_kernel<2><<<dim3(32, 32, 1), tb>>>(ws2, wt + OFF_S2, FS_, D_);
    wtrans_kernel<2><<<dim3(128, 16, 8), tb>>>(w1, wt + OFF_W1, D_, F_);
    wtrans_kernel<2><<<dim3(32, 64, 8), tb>>>(w2, wt + OFF_W2, F_, D_);

    // ---- attention block ----
    ln_kernel<3, false><<<T_, 256>>>(x, ln1_g, ln1_b, nullptr, xn1p);
    hgemm<3, 3>(xn1p, wt + OFF_Q, bqkv, nullptr, nullptr, qkvp,
                T_, D_, D_, 3, TD, 0, 3LL * MEG, D_, 3LL * (long long)TD, TD);
    attn_hmma_kernel<<<dim3(S_ / 128, H_, B_), 256, ATTN_SM>>>(
        qkvp, qkvp + 3 * TD, qkvp + 6 * TD, mask, attnp);
    hgemm<3, 1>(attnp, wt + OFF_O, bo, x, x1, nullptr,
                T_, D_, D_, 1, TD, 0, 0, 0, 0, 0);

    // ---- MoE block ----
    ln_kernel<2, true><<<T_, 256>>>(x1, ln2_g, ln2_b, xn2, xn2p);
    router_kernel<<<T_, 256>>>(xn2, wrout, eidx, gate);
    pos_kernel<<<E_, 256>>>(eidx, pos);
    scatter_kernel<<<NKT, 256>>>(xn2p, eidx, pos, dispp);
    hgemm<2, 2>(dispp, wt + OFF_W1, b1, nullptr, nullptr, hbufp,
                CAP_, F_, D_, E_,
                (long long)E_ * CAP_ * D_, (long long)CAP_ * D_, 2LL * D_ * F_, F_,
                (long long)CAP_ * F_, (long long)E_ * CAP_ * F_);
    hgemm<2, 0>(hbufp, wt + OFF_W2, b2, nullptr, eo, nullptr,
                CAP_, D_, F_, E_,
                (long long)E_ * CAP_ * F_, (long long)CAP_ * F_, 2LL * F_ * D_, D_,
                (long long)CAP_ * D_, 0);

    // ---- shared expert ----
    hgemm<2, 2>(xn2p, wt + OFF_S1, bs1, nullptr, nullptr, sh1p,
                T_, FS_, D_, 1, TD, 0, 0, 0, 0, (long long)T_ * FS_);
    hgemm<2, 0>(sh1p, wt + OFF_S2, bs2, nullptr, sh2, nullptr,
                T_, D_, FS_, 1, (long long)T_ * FS_, 0, 0, 0, 0, 0);

    // ---- combine ----
    combine_kernel<<<T_, 256>>>(x1, sh2, eo, eidx, pos, gate, out);
}

// round 15
// speedup vs baseline: 1.1191x; 1.1191x over previous
#include <cuda_runtime.h>
#include <cuda_bf16.h>
#include <math.h>
#include <stdint.h>

#define B_   4
#define S_   2048
#define D_   1024
#define H_   16
#define HD_  64
#define E_   8
#define F_   4096
#define FS_  2048
#define T_   (B_*S_)
#define CAP_ 2560
#define NKT  (2*T_)
#define TD   ((size_t)T_*D_)

// fp32 scratch
__device__ float g_qkv [3*T_*D_];
__device__ float g_x1  [T_*D_];
__device__ float g_xn2 [T_*D_];
__device__ float g_sh2 [T_*D_];
__device__ float g_eo  [(size_t)E_*CAP_*D_];
__device__ float g_bqkv[3*D_];
__device__ int   g_eidx[NKT];
__device__ int   g_pos [NKT];
__device__ float g_gate[NKT];
// bf16 split planes
__device__ __nv_bfloat16 g_xn1p [3*(size_t)T_*D_];
__device__ __nv_bfloat16 g_attnp[3*(size_t)T_*D_];
__device__ __nv_bfloat16 g_xn2p [2*(size_t)T_*D_];
__device__ __nv_bfloat16 g_dispp[2*(size_t)E_*CAP_*D_];
__device__ __nv_bfloat16 g_hbufp[2*(size_t)E_*CAP_*F_];
__device__ __nv_bfloat16 g_sh1p [2*(size_t)T_*FS_];

#define MEG (1024ULL*1024ULL)
#define OFF_Q  0ULL
#define OFF_Kw (3ULL*MEG)
#define OFF_V  (6ULL*MEG)
#define OFF_O  (9ULL*MEG)
#define OFF_S1 (12ULL*MEG)
#define OFF_S2 (16ULL*MEG)
#define OFF_W1 (20ULL*MEG)
#define OFF_W2 (84ULL*MEG)
#define WT_TOT (148ULL*MEG)
__device__ __nv_bfloat16 g_wt[WT_TOT];

__device__ __forceinline__ float gelu_exact(float v) {
    return 0.5f * v * (1.0f + erff(v * 0.7071067811865476f));
}
__device__ __forceinline__ uint32_t s2u(const void* p) {
    uint32_t a;
    asm("{ .reg .u64 t; cvta.to.shared.u64 t, %1; cvt.u32.u64 %0, t; }" : "=r"(a) : "l"(p));
    return a;
}
__device__ __forceinline__ uint32_t pk2(__nv_bfloat16 a, __nv_bfloat16 b) {
    return (uint32_t)__bfloat16_as_ushort(a) | ((uint32_t)__bfloat16_as_ushort(b) << 16);
}
__device__ __forceinline__ void mma16816(float* d, const uint32_t* a, const uint32_t* b) {
    asm volatile("mma.sync.aligned.m16n8k16.row.col.f32.bf16.bf16.f32 "
        "{%0,%1,%2,%3}, {%4,%5,%6,%7}, {%8,%9}, {%0,%1,%2,%3};"
        : "+f"(d[0]), "+f"(d[1]), "+f"(d[2]), "+f"(d[3])
        : "r"(a[0]), "r"(a[1]), "r"(a[2]), "r"(a[3]), "r"(b[0]), "r"(b[1]));
}
#define LDSM_X4(r, addr) \
    asm volatile("ldmatrix.sync.aligned.m8n8.x4.shared.b16 {%0,%1,%2,%3}, [%4];" \
        : "=r"((r)[0]), "=r"((r)[1]), "=r"((r)[2]), "=r"((r)[3]) : "r"(addr))
#define LDSM_X4T(r, addr) \
    asm volatile("ldmatrix.sync.aligned.m8n8.x4.trans.shared.b16 {%0,%1,%2,%3}, [%4];" \
        : "=r"((r)[0]), "=r"((r)[1]), "=r"((r)[2]), "=r"((r)[3]) : "r"(addr))
#define CP16(smaddr, gptr) \
    asm volatile("cp.async.ca.shared.global [%0], [%1], 16;" :: "r"(smaddr), "l"(gptr))
#define CP_COMMIT() asm volatile("cp.async.commit_group;" ::: "memory")
#define CP_WAIT0()  asm volatile("cp.async.wait_group 0;" ::: "memory")

// ===== weight transpose + split: W[K,N] -> Wt[s][n][k], 64k x 32n tiles, uint4 stores =====
template<int NS>
__global__ void wtrans_kernel(const float* __restrict__ W, __nv_bfloat16* __restrict__ Wt,
                              int K, int N)
{
    __shared__ float t[64][33];
    const long long wb = (long long)blockIdx.z * K * N;
    __nv_bfloat16* out = Wt + (long long)blockIdx.z * NS * (long long)K * N;
    const long long plane = (long long)K * N;
    const int n0 = blockIdx.x * 32, k0 = blockIdx.y * 64;
    #pragma unroll
    for (int jj = 0; jj < 8; jj++)
        t[threadIdx.y + 8 * jj][threadIdx.x] =
            W[wb + (long long)(k0 + threadIdx.y + 8 * jj) * N + n0 + threadIdx.x];
    __syncthreads();
    const int tid = threadIdx.y * 32 + threadIdx.x;
    const int n_loc = tid >> 3, k8 = (tid & 7) * 8;
    float v[8];
    #pragma unroll
    for (int e = 0; e < 8; e++) v[e] = t[k8 + e][n_loc];
    const long long o = (long long)(n0 + n_loc) * K + k0 + k8;
    #pragma unroll
    for (int s = 0; s < NS; s++) {
        __nv_bfloat16 h[8];
        #pragma unroll
        for (int e = 0; e < 8; e++) {
            h[e] = __float2bfloat16(v[e]);
            if (s + 1 < NS) v[e] -= __bfloat162float(h[e]);
        }
        uint4 pkv;
        pkv.x = pk2(h[0], h[1]); pkv.y = pk2(h[2], h[3]);
        pkv.z = pk2(h[4], h[5]); pkv.w = pk2(h[6], h[7]);
        *(uint4*)(out + s * plane + o) = pkv;
    }
}

// ===== HMMA GEMM: both operands pre-split bf16 planes, full cp.async =====
// OUT: 0 = fp32, 1 = fp32+residual, 2 = gelu + split2 bf16 planes
#define RS 40
#define PLB (128*RS*2)

template<int NS, int OUT>
__global__ __launch_bounds__(256, (NS == 2) ? 2 : 1)
void hmma_gemm_kernel(const __nv_bfloat16* __restrict__ Ap, const __nv_bfloat16* __restrict__ Bt,
                      const float* __restrict__ bias, const float* __restrict__ Rsrc,
                      float* __restrict__ Cf, __nv_bfloat16* __restrict__ Cp,
                      int N, int K,
                      long long planeA, long long sAb, long long sBb, long long sBias,
                      long long sCb, long long planeC)
{
    extern __shared__ __align__(16) char sm[];
    const int tid = threadIdx.x, wid = tid >> 5, lane = tid & 31;
    const int STG = 2 * NS * PLB;

    Ap   += (long long)blockIdx.z * sAb;
    Bt   += (long long)blockIdx.z * sBb;
    bias += (long long)blockIdx.z * sBias;
    if (OUT == 2) Cp += (long long)blockIdx.z * sCb;
    else          Cf += (long long)blockIdx.z * sCb;
    if (OUT == 1) Rsrc += (long long)blockIdx.z * sCb;

    const long long planeB = (long long)N * K;
    const int rowBase = blockIdx.y * 128, colBase = blockIdx.x * 128;
    const uint32_t smb = s2u(sm);

    const int lr = tid >> 1, kh = (tid & 1) * 16;
    const __nv_bfloat16* aRow = Ap + (long long)(rowBase + lr) * K + kh;
    const __nv_bfloat16* bRow = Bt + (long long)(colBase + lr) * K + kh;
    const uint32_t aOff = (uint32_t)(lr * (RS * 2) + kh * 2);
    const uint32_t bOff = (uint32_t)(NS * PLB + lr * (RS * 2) + kh * 2);

    const int wm = (wid & 3) * 32, wn = (wid >> 2) * 64;
    const uint32_t aFragO = (uint32_t)((wm + (lane & 15)) * (RS * 2) + ((lane >> 4) * 8) * 2);
    const uint32_t bFragO = (uint32_t)(NS * PLB
        + (wn + (lane >> 4) * 8 + (lane & 7)) * (RS * 2) + ((lane >> 3) & 1) * 16);

    float acc[2][8][4];
    #pragma unroll
    for (int mi = 0; mi < 2; mi++)
        #pragma unroll
        for (int ni = 0; ni < 8; ni++)
            #pragma unroll
            for (int c = 0; c < 4; c++) acc[mi][ni][c] = 0.f;

    const int nIter = K >> 5;

    #pragma unroll
    for (int s = 0; s < NS; s++) {
        CP16(smb + s * PLB + aOff,      aRow + s * planeA);
        CP16(smb + s * PLB + aOff + 16, aRow + s * planeA + 8);
        CP16(smb + s * PLB + bOff,      bRow + s * planeB);
        CP16(smb + s * PLB + bOff + 16, bRow + s * planeB + 8);
    }
    CP_COMMIT();

    for (int it = 0; it < nIter; ++it) {
        const uint32_t sb = smb + (uint32_t)(it & 1) * STG;
        CP_WAIT0();
        __syncthreads();

        if (it + 1 < nIter) {
            const int kn = (it + 1) << 5;
            const uint32_t sn = smb + (uint32_t)((it + 1) & 1) * STG;
            #pragma unroll
            for (int s = 0; s < NS; s++) {
                CP16(sn + s * PLB + aOff,      aRow + s * planeA + kn);
                CP16(sn + s * PLB + aOff + 16, aRow + s * planeA + kn + 8);
                CP16(sn + s * PLB + bOff,      bRow + s * planeB + kn);
                CP16(sn + s * PLB + bOff + 16, bRow + s * planeB + kn + 8);
            }
            CP_COMMIT();
        }

        #pragma unroll
        for (int kk = 0; kk < 32; kk += 16) {
            uint32_t af[NS][2][4];
            #pragma unroll
            for (int i = 0; i < NS; i++)
                #pragma unroll
                for (int mi = 0; mi < 2; mi++)
                    LDSM_X4(af[i][mi], sb + i * PLB + aFragO + (mi * 16) * (RS * 2) + kk * 2);
            #pragma unroll
            for (int j = 0; j < NS; j++) {
                uint32_t bfr[16];
                #pragma unroll
                for (int p = 0; p < 4; p++)
                    LDSM_X4(bfr + p * 4, sb + j * PLB + bFragO + (p * 16) * (RS * 2) + kk * 2);
                #pragma unroll
                for (int i = 0; i < NS; i++) {
                    if (i + j >= NS) continue;
                    #pragma unroll
                    for (int mi = 0; mi < 2; mi++)
                        #pragma unroll
                        for (int ni = 0; ni < 8; ni++)
                            mma16816(acc[mi][ni], af[i][mi],
                                     bfr + (ni >> 1) * 4 + (ni & 1) * 2);
                }
            }
        }
        __syncthreads();
    }

    #pragma unroll
    for (int mi = 0; mi < 2; mi++) {
        #pragma unroll
        for (int half = 0; half < 2; half++) {
            const int r = rowBase + wm + mi * 16 + (lane >> 2) + half * 8;
            const long long cidx = (long long)r * N + colBase + wn + (lane & 3) * 2;
            const float* bp = bias + colBase + wn + (lane & 3) * 2;
            #pragma unroll
            for (int ni = 0; ni < 8; ni++) {
                float x0 = acc[mi][ni][half * 2 + 0] + bp[ni * 8];
                float x1 = acc[mi][ni][half * 2 + 1] + bp[ni * 8 + 1];
                if (OUT == 2) {
                    x0 = gelu_exact(x0); x1 = gelu_exact(x1);
                    __nv_bfloat16 h0 = __float2bfloat16(x0), h1 = __float2bfloat16(x1);
                    __nv_bfloat16 l0 = __float2bfloat16(x0 - __bfloat162float(h0));
                    __nv_bfloat16 l1 = __float2bfloat16(x1 - __bfloat162float(h1));
                    *(uint32_t*)(Cp + cidx + ni * 8)          = pk2(h0, h1);
                    *(uint32_t*)(Cp + planeC + cidx + ni * 8) = pk2(l0, l1);
                } else {
                    if (OUT == 1) {
                        float2 rr = *(const float2*)(Rsrc + cidx + ni * 8);
                        x0 += rr.x; x1 += rr.y;
                    }
                    float2 o2; o2.x = x0; o2.y = x1;
                    *(float2*)(Cf + cidx + ni * 8) = o2;
                }
            }
        }
    }
}

// ===== HMMA flash attention (R12 version: fp32 K/V load + in-loop split) =====
#define ARS 72
#define QPL (128*ARS*2)
#define KPL (64*ARS*2)
#define ATTN_SM (3*QPL + 6*KPL)

__global__ __launch_bounds__(256)
void attn_hmma_kernel(const float* __restrict__ Qg, const float* __restrict__ Kg,
                      const float* __restrict__ Vg, const unsigned char* __restrict__ mask,
                      __nv_bfloat16* __restrict__ Op)
{
    extern __shared__ __align__(16) char smr[];
    const int tid = threadIdx.x, wid = tid >> 5, lane = tid & 31;
    const int h = blockIdx.y, b = blockIdx.z;
    const size_t qrow0 = (size_t)b * S_ + blockIdx.x * 128;
    const uint32_t uQ = s2u(smr), uK = uQ + 3 * QPL, uV = uK + 3 * KPL;

    {
        const int r = tid >> 1, c = (tid & 1) * 32;
        const float* src = Qg + (qrow0 + r) * D_ + h * HD_ + c;
        float v[32];
        #pragma unroll
        for (int q = 0; q < 8; q++) *(float4*)(v + q * 4) = *(const float4*)(src + q * 4);
        #pragma unroll
        for (int e = 0; e < 32; e++) v[e] *= 0.125f;
        char* dst = smr + r * (ARS * 2) + c * 2;
        #pragma unroll
        for (int s = 0; s < 3; s++) {
            __nv_bfloat16 hh[32];
            #pragma unroll
            for (int e = 0; e < 32; e++) {
                hh[e] = __float2bfloat16(v[e]);
                if (s < 2) v[e] -= __bfloat162float(hh[e]);
            }
            #pragma unroll
            for (int q = 0; q < 4; q++) {
                uint4 pkv;
                pkv.x = pk2(hh[q*8+0], hh[q*8+1]); pkv.y = pk2(hh[q*8+2], hh[q*8+3]);
                pkv.z = pk2(hh[q*8+4], hh[q*8+5]); pkv.w = pk2(hh[q*8+6], hh[q*8+7]);
                *(uint4*)(dst + s * QPL + q * 16) = pkv;
            }
        }
    }

    float o[8][4];
    #pragma unroll
    for (int nf = 0; nf < 8; nf++)
        #pragma unroll
        for (int c = 0; c < 4; c++) o[nf][c] = 0.f;
    float mrun0 = -1e30f, mrun1 = -1e30f, l0 = 0.f, l1 = 0.f;

    const int kr = tid >> 2, kq = (tid & 3) * 16;
    const int grp = lane >> 3;

    for (int j = 0; j < S_ / 64; j++) {
        __syncthreads();
        {
            const size_t base = (size_t)(b * S_ + j * 64 + kr) * D_ + h * HD_ + kq;
            float kv[16], vv[16];
            #pragma unroll
            for (int q = 0; q < 4; q++) {
                *(float4*)(kv + q * 4) = *(const float4*)(Kg + base + q * 4);
                *(float4*)(vv + q * 4) = *(const float4*)(Vg + base + q * 4);
            }
            char* kd = smr + 3 * QPL + kr * (ARS * 2) + kq * 2;
            char* vd = kd + 3 * KPL;
            #pragma unroll
            for (int s = 0; s < 3; s++) {
                __nv_bfloat16 hk[16], hv[16];
                #pragma unroll
                for (int e = 0; e < 16; e++) {
                    hk[e] = __float2bfloat16(kv[e]);
                    hv[e] = __float2bfloat16(vv[e]);
                    if (s < 2) { kv[e] -= __bfloat162float(hk[e]); vv[e] -= __bfloat162float(hv[e]); }
                }
                uint4 a, bb;
                a.x = pk2(hk[0],hk[1]); a.y = pk2(hk[2],hk[3]); a.z = pk2(hk[4],hk[5]); a.w = pk2(hk[6],hk[7]);
                *(uint4*)(kd + s * KPL) = a;
                a.x = pk2(hk[8],hk[9]); a.y = pk2(hk[10],hk[11]); a.z = pk2(hk[12],hk[13]); a.w = pk2(hk[14],hk[15]);
                *(uint4*)(kd + s * KPL + 16) = a;
                bb.x = pk2(hv[0],hv[1]); bb.y = pk2(hv[2],hv[3]); bb.z = pk2(hv[4],hv[5]); bb.w = pk2(hv[6],hv[7]);
                *(uint4*)(vd + s * KPL) = bb;
                bb.x = pk2(hv[8],hv[9]); bb.y = pk2(hv[10],hv[11]); bb.z = pk2(hv[12],hv[13]); bb.w = pk2(hv[14],hv[15]);
                *(uint4*)(vd + s * KPL + 16) = bb;
            }
        }
        __syncthreads();

        float sacc[8][4];
        #pragma unroll
        for (int nf = 0; nf < 8; nf++)
            #pragma unroll
            for (int c = 0; c < 4; c++) sacc[nf][c] = 0.f;

        #pragma unroll
        for (int jpl = 0; jpl < 3; jpl++) {
            #pragma unroll
            for (int kf = 0; kf < 4; kf++) {
                uint32_t kb[16];
                #pragma unroll
                for (int nfp = 0; nfp < 4; nfp++) {
                    uint32_t addr = uK + jpl * KPL
                        + (uint32_t)((nfp * 16 + (grp >> 1) * 8 + (lane & 7)) * (ARS * 2))
                        + kf * 32 + (grp & 1) * 16;
                    LDSM_X4(kb + nfp * 4, addr);
                }
                #pragma unroll
                for (int ipl = 0; ipl < 3; ipl++) {
                    if (ipl + jpl >= 3) continue;
                    uint32_t aq[4];
                    uint32_t qaddr = uQ + ipl * QPL
                        + (uint32_t)((wid * 16 + (lane & 15)) * (ARS * 2))
                        + kf * 32 + (lane >> 4) * 16;
                    LDSM_X4(aq, qaddr);
                    #pragma unroll
                    for (int nf = 0; nf < 8; nf++)
                        mma16816(sacc[nf], aq, kb + (nf >> 1) * 4 + (nf & 1) * 2);
                }
            }
        }

        const unsigned char* mrow = mask + b * S_ + j * 64;
        #pragma unroll
        for (int nf = 0; nf < 8; nf++) {
            uchar2 mm = *(const uchar2*)(mrow + nf * 8 + (lane & 3) * 2);
            if (mm.x) { sacc[nf][0] = -1e30f; sacc[nf][2] = -1e30f; }
            if (mm.y) { sacc[nf][1] = -1e30f; sacc[nf][3] = -1e30f; }
        }
        float nm0 = mrun0, nm1 = mrun1;
        #pragma unroll
        for (int nf = 0; nf < 8; nf++) {
            nm0 = fmaxf(nm0, fmaxf(sacc[nf][0], sacc[nf][1]));
            nm1 = fmaxf(nm1, fmaxf(sacc[nf][2], sacc[nf][3]));
        }
        nm0 = fmaxf(nm0, __shfl_xor_sync(0xffffffffu, nm0, 1));
        nm0 = fmaxf(nm0, __shfl_xor_sync(0xffffffffu, nm0, 2));
        nm1 = fmaxf(nm1, __shfl_xor_sync(0xffffffffu, nm1, 1));
        nm1 = fmaxf(nm1, __shfl_xor_sync(0xffffffffu, nm1, 2));
        const float al0 = __expf(mrun0 - nm0), al1 = __expf(mrun1 - nm1);
        mrun0 = nm0; mrun1 = nm1;
        float ps0 = 0.f, ps1 = 0.f;
        #pragma unroll
        for (int nf = 0; nf < 8; nf++) {
            sacc[nf][0] = __expf(sacc[nf][0] - nm0); ps0 += sacc[nf][0];
            sacc[nf][1] = __expf(sacc[nf][1] - nm0); ps0 += sacc[nf][1];
            sacc[nf][2] = __expf(sacc[nf][2] - nm1); ps1 += sacc[nf][2];
            sacc[nf][3] = __expf(sacc[nf][3] - nm1); ps1 += sacc[nf][3];
        }
        ps0 += __shfl_xor_sync(0xffffffffu, ps0, 1);
        ps0 += __shfl_xor_sync(0xffffffffu, ps0, 2);
        ps1 += __shfl_xor_sync(0xffffffffu, ps1, 1);
        ps1 += __shfl_xor_sync(0xffffffffu, ps1, 2);
        l0 = l0 * al0 + ps0;
        l1 = l1 * al1 + ps1;
        #pragma unroll
        for (int nf = 0; nf < 8; nf++) {
            o[nf][0] *= al0; o[nf][1] *= al0; o[nf][2] *= al1; o[nf][3] *= al1;
        }

        uint32_t pa[3][4][4];
        #pragma unroll
        for (int kf = 0; kf < 4; kf++) {
            float e[8];
            e[0] = sacc[2*kf][0];   e[1] = sacc[2*kf][1];
            e[2] = sacc[2*kf][2];   e[3] = sacc[2*kf][3];
            e[4] = sacc[2*kf+1][0]; e[5] = sacc[2*kf+1][1];
            e[6] = sacc[2*kf+1][2]; e[7] = sacc[2*kf+1][3];
            #pragma unroll
            for (int pl = 0; pl < 3; pl++) {
                __nv_bfloat16 hh[8];
                #pragma unroll
                for (int q = 0; q < 8; q++) {
                    hh[q] = __float2bfloat16(e[q]);
                    if (pl < 2) e[q] -= __bfloat162float(hh[q]);
                }
                pa[pl][kf][0] = pk2(hh[0], hh[1]);
                pa[pl][kf][1] = pk2(hh[2], hh[3]);
                pa[pl][kf][2] = pk2(hh[4], hh[5]);
                pa[pl][kf][3] = pk2(hh[6], hh[7]);
            }
        }

        #pragma unroll
        for (int vpl = 0; vpl < 3; vpl++) {
            #pragma unroll
            for (int kf = 0; kf < 4; kf++) {
                uint32_t vb[16];
                #pragma unroll
                for (int nfp = 0; nfp < 4; nfp++) {
                    uint32_t addr = uV + vpl * KPL
                        + (uint32_t)((kf * 16 + (grp & 1) * 8 + (lane & 7)) * (ARS * 2))
                        + (2 * nfp + (grp >> 1)) * 16;
                    LDSM_X4T(vb + nfp * 4, addr);
                }
                #pragma unroll
                for (int ppl = 0; ppl < 3; ppl++) {
                    if (ppl + vpl >= 3) continue;
                    #pragma unroll
                    for (int nf = 0; nf < 8; nf++)
                        mma16816(o[nf], pa[ppl][kf], vb + (nf >> 1) * 4 + (nf & 1) * 2);
                }
            }
        }
    }

    const float inv0 = (l0 > 0.f) ? 1.f / l0 : 0.f;
    const float inv1 = (l1 > 0.f) ? 1.f / l1 : 0.f;
    const size_t row0 = qrow0 + wid * 16 + (lane >> 2);
    const size_t idx0 = row0 * D_ + h * HD_ + (lane & 3) * 2;
    const size_t idx1 = idx0 + 8 * D_;
    #pragma unroll
    for (int nf = 0; nf < 8; nf++) {
        float vx = o[nf][0] * inv0, vy = o[nf][1] * inv0;
        float wx = o[nf][2] * inv1, wy = o[nf][3] * inv1;
        #pragma unroll
        for (int pl = 0; pl < 3; pl++) {
            __nv_bfloat16 hx = __float2bfloat16(vx), hy = __float2bfloat16(vy);
            __nv_bfloat16 gx = __float2bfloat16(wx), gy = __float2bfloat16(wy);
            if (pl < 2) {
                vx -= __bfloat162float(hx); vy -= __bfloat162float(hy);
                wx -= __bfloat162float(gx); wy -= __bfloat162float(gy);
            }
            *(uint32_t*)(Op + pl * TD + idx0 + nf * 8) = pk2(hx, hy);
            *(uint32_t*)(Op + pl * TD + idx1 + nf * 8) = pk2(gx, gy);
        }
    }
}

// ===== LayerNorm -> bf16 planes (+ optional fp32) =====
template<int NS, bool F32>
__global__ void ln_kernel(const float* __restrict__ x, const float* __restrict__ g,
                          const float* __restrict__ b, float* __restrict__ outf,
                          __nv_bfloat16* __restrict__ outp)
{
    const int t = blockIdx.x, tid = threadIdx.x;
    const float* xr = x + (size_t)t * D_;
    const int i0 = tid * 4;
    float4 xv = *(const float4*)(xr + i0);
    float s  = xv.x + xv.y + xv.z + xv.w;
    float s2 = xv.x * xv.x + xv.y * xv.y + xv.z * xv.z + xv.w * xv.w;
    __shared__ float sm1[8], sm2[8];
    #pragma unroll
    for (int o = 16; o > 0; o >>= 1) {
        s  += __shfl_down_sync(0xffffffffu, s,  o);
        s2 += __shfl_down_sync(0xffffffffu, s2, o);
    }
    const int wid = tid >> 5, lane = tid & 31;
    if (lane == 0) { sm1[wid] = s; sm2[wid] = s2; }
    __syncthreads();
    if (tid == 0) {
        float a = 0.f, c = 0.f;
        #pragma unroll
        for (int w = 0; w < 8; w++) { a += sm1[w]; c += sm2[w]; }
        sm1[0] = a; sm2[0] = c;
    }
    __syncthreads();
    const float mean = sm1[0] * (1.f / D_);
    const float var  = sm2[0] * (1.f / D_) - mean * mean;
    const float rstd = rsqrtf(var + 1e-5f);
    float4 gv = *(const float4*)(g + i0);
    float4 bv = *(const float4*)(b + i0);
    float y[4];
    y[0] = (xv.x - mean) * rstd * gv.x + bv.x;
    y[1] = (xv.y - mean) * rstd * gv.y + bv.y;
    y[2] = (xv.z - mean) * rstd * gv.z + bv.z;
    y[3] = (xv.w - mean) * rstd * gv.w + bv.w;
    if (F32) *(float4*)(outf + (size_t)t * D_ + i0) = *(float4*)y;
    float v[4] = {y[0], y[1], y[2], y[3]};
    #pragma unroll
    for (int sp = 0; sp < NS; sp++) {
        __nv_bfloat16 h[4];
        #pragma unroll
        for (int e = 0; e < 4; e++) {
            h[e] = __float2bfloat16(v[e]);
            if (sp + 1 < NS) v[e] -= __bfloat162float(h[e]);
        }
        uint2 pkv; pkv.x = pk2(h[0], h[1]); pkv.y = pk2(h[2], h[3]);
        *(uint2*)(outp + (size_t)sp * TD + (size_t)t * D_ + i0) = pkv;
    }
}

// ===== router =====
__global__ void router_kernel(const float* __restrict__ xn, const float* __restrict__ wr,
                              int* __restrict__ eidx, float* __restrict__ gate)
{
    const int t = blockIdx.x;
    float acc[E_];
    #pragma unroll
    for (int e = 0; e < E_; e++) acc[e] = 0.f;
    const float* xr = xn + (size_t)t * D_;
    for (int i = threadIdx.x; i < D_; i += 256) {
        const float xv = xr[i];
        const float* wrow = wr + (size_t)i * E_;
        #pragma unroll
        for (int e = 0; e < E_; e++) acc[e] += xv * wrow[e];
    }
    __shared__ float red[8][E_];
    #pragma unroll
    for (int e = 0; e < E_; e++)
        #pragma unroll
        for (int o = 16; o > 0; o >>= 1)
            acc[e] += __shfl_down_sync(0xffffffffu, acc[e], o);
    const int wid = threadIdx.x >> 5, lane = threadIdx.x & 31;
    if (lane == 0)
        #pragma unroll
        for (int e = 0; e < E_; e++) red[wid][e] = acc[e];
    __syncthreads();
    if (threadIdx.x == 0) {
        float lg[E_];
        #pragma unroll
        for (int e = 0; e < E_; e++) {
            float s = 0.f;
            #pragma unroll
            for (int w = 0; w < 8; w++) s += red[w][e];
            lg[e] = s;
        }
        float m = lg[0];
        #pragma unroll
        for (int e = 1; e < E_; e++) m = fmaxf(m, lg[e]);
        float p[E_], sum = 0.f;
        #pragma unroll
        for (int e = 0; e < E_; e++) { p[e] = expf(lg[e] - m); sum += p[e]; }
        const float invs = 1.f / sum;
        #pragma unroll
        for (int e = 0; e < E_; e++) p[e] *= invs;
        int e0 = 0;
        #pragma unroll
        for (int e = 1; e < E_; e++) if (p[e] > p[e0]) e0 = e;
        int e1 = (e0 == 0) ? 1 : 0;
        #pragma unroll
        for (int e = 0; e < E_; e++) if (e != e0 && p[e] > p[e1]) e1 = e;
        const float v0 = p[e0], v1 = p[e1];
        const float inv = 1.f / (v0 + v1);
        eidx[t]      = e0; gate[t]      = v0 * inv;
        eidx[T_ + t] = e1; gate[T_ + t] = v1 * inv;
    }
}

__global__ void pos_kernel(const int* __restrict__ eidx, int* __restrict__ pos)
{
    const int e = blockIdx.x;
    __shared__ int cnts[256];
    const int base = threadIdx.x * 64;
    int c = 0;
    for (int i = 0; i < 64; i++) c += (eidx[base + i] == e) ? 1 : 0;
    cnts[threadIdx.x] = c;
    __syncthreads();
    if (threadIdx.x == 0) {
        int run = 0;
        for (int k = 0; k < 256; k++) { int v = cnts[k]; cnts[k] = run; run += v; }
    }
    __syncthreads();
    int run = cnts[threadIdx.x];
    for (int i = 0; i < 64; i++)
        if (eidx[base + i] == e) pos[base + i] = run++;
}

__global__ void scatter_kernel(const __nv_bfloat16* __restrict__ xp, const int* __restrict__ eidx,
                               const int* __restrict__ pos, __nv_bfloat16* __restrict__ dp)
{
    const int i = blockIdx.x;
    const int p = pos[i];
    if (p >= CAP_) return;
    const int e = eidx[i];
    const int t = i & (T_ - 1);
    const size_t PL = (size_t)E_ * CAP_ * D_;
    #pragma unroll
    for (int pl = 0; pl < 2; pl++) {
        const uint2* src = (const uint2*)(xp + (size_t)pl * TD + (size_t)t * D_);
        uint2* dst = (uint2*)(dp + pl * PL + ((size_t)e * CAP_ + p) * D_);
        dst[threadIdx.x] = src[threadIdx.x];
    }
}

__global__ void combine_kernel(const float* __restrict__ x1, const float* __restrict__ sh2,
                               const float* __restrict__ eo, const int* __restrict__ eidx,
                               const int* __restrict__ pos, const float* __restrict__ gate,
                               float* __restrict__ out)
{
    const int t = blockIdx.x;
    const int i0 = t, i1 = T_ + t;
    const int p0 = pos[i0], p1 = pos[i1];
    const float w0 = (p0 < CAP_) ? gate[i0] : 0.f;
    const float w1 = (p1 < CAP_) ? gate[i1] : 0.f;
    const float* e0p = eo + ((size_t)eidx[i0] * CAP_ + min(p0, CAP_ - 1)) * D_;
    const float* e1p = eo + ((size_t)eidx[i1] * CAP_ + min(p1, CAP_ - 1)) * D_;
    const size_t off = (size_t)t * D_;
    for (int d = threadIdx.x; d < D_; d += 256)
        out[off + d] = x1[off + d] + sh2[off + d] + w0 * e0p[d] + w1 * e1p[d];
}

// ===== host =====
template<int NS, int OUT>
static void hgemm(const __nv_bfloat16* Ap, const __nv_bfloat16* Bt, const float* bias,
                  const float* R, float* Cf, __nv_bfloat16* Cp,
                  int M, int N, int K, int batch,
                  long long planeA, long long sAb, long long sBb, long long sBias,
                  long long sCb, long long planeC)
{
    const int smem = 4 * NS * PLB;
    static bool init[2][3] = {};
    if (!init[NS - 2][OUT]) {
        cudaFuncSetAttribute(hmma_gemm_kernel<NS, OUT>,
                             cudaFuncAttributeMaxDynamicSharedMemorySize, smem);
        init[NS - 2][OUT] = true;
    }
    dim3 grid(N / 128, M / 128, batch);
    hmma_gemm_kernel<NS, OUT><<<grid, 256, smem>>>(Ap, Bt, bias, R, Cf, Cp, N, K,
                                                   planeA, sAb, sBb, sBias, sCb, planeC);
}

extern "C" void kernel_launch(void* const* d_in, const int* in_sizes, int n_in,
                              void* d_out, int out_size)
{
    const float* x      = (const float*)d_in[0];
    const unsigned char* mask = (const unsigned char*)d_in[1];
    const float* ln1_g  = (const float*)d_in[2];
    const float* ln1_b  = (const float*)d_in[3];
    const float* wq     = (const float*)d_in[4];
    const float* bq     = (const float*)d_in[5];
    const float* wk     = (const float*)d_in[6];
    const float* bk     = (const float*)d_in[7];
    const float* wv     = (const float*)d_in[8];
    const float* bv     = (const float*)d_in[9];
    const float* wo     = (const float*)d_in[10];
    const float* bo     = (const float*)d_in[11];
    const float* ln2_g  = (const float*)d_in[12];
    const float* ln2_b  = (const float*)d_in[13];
    const float* wrout  = (const float*)d_in[14];
    const float* w1     = (const float*)d_in[15];
    const float* b1     = (const float*)d_in[16];
    const float* w2     = (const float*)d_in[17];
    const float* b2     = (const float*)d_in[18];
    const float* ws1    = (const float*)d_in[19];
    const float* bs1    = (const float*)d_in[20];
    const float* ws2    = (const float*)d_in[21];
    const float* bs2    = (const float*)d_in[22];
    float* out = (float*)d_out;

    float *qkv, *x1, *xn2, *sh2, *eo, *gate, *bqkv;
    int *eidx, *pos;
    __nv_bfloat16 *wt, *xn1p, *attnp, *xn2p, *dispp, *hbufp, *sh1p;
    cudaGetSymbolAddress((void**)&qkv,   g_qkv);
    cudaGetSymbolAddress((void**)&x1,    g_x1);
    cudaGetSymbolAddress((void**)&xn2,   g_xn2);
    cudaGetSymbolAddress((void**)&sh2,   g_sh2);
    cudaGetSymbolAddress((void**)&eo,    g_eo);
    cudaGetSymbolAddress((void**)&gate,  g_gate);
    cudaGetSymbolAddress((void**)&bqkv,  g_bqkv);
    cudaGetSymbolAddress((void**)&eidx,  g_eidx);
    cudaGetSymbolAddress((void**)&pos,   g_pos);
    cudaGetSymbolAddress((void**)&wt,    g_wt);
    cudaGetSymbolAddress((void**)&xn1p,  g_xn1p);
    cudaGetSymbolAddress((void**)&attnp, g_attnp);
    cudaGetSymbolAddress((void**)&xn2p,  g_xn2p);
    cudaGetSymbolAddress((void**)&dispp, g_dispp);
    cudaGetSymbolAddress((void**)&hbufp, g_hbufp);
    cudaGetSymbolAddress((void**)&sh1p,  g_sh1p);

    static bool ainit = false;
    if (!ainit) {
        cudaFuncSetAttribute(attn_hmma_kernel, cudaFuncAttributeMaxDynamicSharedMemorySize, ATTN_SM);
        ainit = true;
    }

    cudaMemcpyAsync(bqkv,          bq, D_ * sizeof(float), cudaMemcpyDeviceToDevice, 0);
    cudaMemcpyAsync(bqkv + D_,     bk, D_ * sizeof(float), cudaMemcpyDeviceToDevice, 0);
    cudaMemcpyAsync(bqkv + 2 * D_, bv, D_ * sizeof(float), cudaMemcpyDeviceToDevice, 0);

    // ---- weight transpose + split (64k x 32n tiles, uint4 stores) ----
    dim3 tb(32, 8);
    wtrans_kernel<3><<<dim3(32, 16, 1), tb>>>(wq,  wt + OFF_Q,  D_, D_);
    wtrans_kernel<3><<<dim3(32, 16, 1), tb>>>(wk,  wt + OFF_Kw, D_, D_);
    wtrans_kernel<3><<<dim3(32, 16, 1), tb>>>(wv,  wt + OFF_V,  D_, D_);
    wtrans_kernel<3><<<dim3(32, 16, 1), tb>>>(wo,  wt + OFF_O,  D_, D_);
    wtrans_kernel<2><<<dim3(64, 16, 1), tb>>>(ws1, wt + OFF_S1, D_, FS_);
    wtrans_kernel<2><<<dim3(32, 32, 1), tb>>>(ws2, wt + OFF_S2, FS_, D_);
    wtrans_kernel<2><<<dim3(128, 16, 8), tb>>>(w1, wt + OFF_W1, D_, F_);
    wtrans_kernel<2><<<dim3(32, 64, 8), tb>>>(w2, wt + OFF_W2, F_, D_);

    // ---- attention block ----
    ln_kernel<3, false><<<T_, 256>>>(x, ln1_g, ln1_b, nullptr, xn1p);
    hgemm<3, 0>(xn1p, wt + OFF_Q, bqkv, nullptr, qkv, nullptr,
                T_, D_, D_, 3, TD, 0, 3LL * MEG, D_, TD, 0);
    attn_hmma_kernel<<<dim3(S_ / 128, H_, B_), 256, ATTN_SM>>>(
        qkv, qkv + TD, qkv + 2 * TD, mask, attnp);
    hgemm<3, 1>(attnp, wt + OFF_O, bo, x, x1, nullptr,
                T_, D_, D_, 1, TD, 0, 0, 0, 0, 0);

    // ---- MoE block ----
    ln_kernel<2, true><<<T_, 256>>>(x1, ln2_g, ln2_b, xn2, xn2p);
    router_kernel<<<T_, 256>>>(xn2, wrout, eidx, gate);
    pos_kernel<<<E_, 256>>>(eidx, pos);
    scatter_kernel<<<NKT, 256>>>(xn2p, eidx, pos, dispp);
    hgemm<2, 2>(dispp, wt + OFF_W1, b1, nullptr, nullptr, hbufp,
                CAP_, F_, D_, E_,
                (long long)E_ * CAP_ * D_, (long long)CAP_ * D_, 2LL * D_ * F_, F_,
                (long long)CAP_ * F_, (long long)E_ * CAP_ * F_);
    hgemm<2, 0>(hbufp, wt + OFF_W2, b2, nullptr, eo, nullptr,
                CAP_, D_, F_, E_,
                (long long)E_ * CAP_ * F_, (long long)CAP_ * F_, 2LL * F_ * D_, D_,
                (long long)CAP_ * D_, 0);

    // ---- shared expert ----
    hgemm<2, 2>(xn2p, wt + OFF_S1, bs1, nullptr, nullptr, sh1p,
                T_, FS_, D_, 1, TD, 0, 0, 0, 0, (long long)T_ * FS_);
    hgemm<2, 0>(sh1p, wt + OFF_S2, bs2, nullptr, sh2, nullptr,
                T_, D_, FS_, 1, (long long)T_ * FS_, 0, 0, 0, 0, 0);

    // ---- combine ----
    combine_kernel<<<T_, 256>>>(x1, sh2, eo, eidx, pos, gate, out);
}

// round 16
// speedup vs baseline: 1.1358x; 1.0149x over previous
#include <cuda_runtime.h>
#include <cuda_bf16.h>
#include <math.h>
#include <stdint.h>

#define B_   4
#define S_   2048
#define D_   1024
#define H_   16
#define HD_  64
#define E_   8
#define F_   4096
#define FS_  2048
#define T_   (B_*S_)
#define CAP_ 2560
#define NKT  (2*T_)
#define TD   ((size_t)T_*D_)

// fp32 scratch
__device__ float g_qkv [3*T_*D_];
__device__ float g_x1  [T_*D_];
__device__ float g_xn2 [T_*D_];
__device__ float g_sh2 [T_*D_];
__device__ float g_eo  [(size_t)E_*CAP_*D_];
__device__ float g_bqkv[3*D_];
__device__ int   g_eidx[NKT];
__device__ int   g_pos [NKT];
__device__ float g_gate[NKT];
// bf16 split planes
__device__ __nv_bfloat16 g_xn1p [3*(size_t)T_*D_];
__device__ __nv_bfloat16 g_attnp[3*(size_t)T_*D_];
__device__ __nv_bfloat16 g_xn2p [2*(size_t)T_*D_];
__device__ __nv_bfloat16 g_dispp[2*(size_t)E_*CAP_*D_];
__device__ __nv_bfloat16 g_hbufp[2*(size_t)E_*CAP_*F_];
__device__ __nv_bfloat16 g_sh1p [2*(size_t)T_*FS_];

#define MEG (1024ULL*1024ULL)
#define OFF_Q  0ULL
#define OFF_Kw (3ULL*MEG)
#define OFF_V  (6ULL*MEG)
#define OFF_O  (9ULL*MEG)
#define OFF_S1 (12ULL*MEG)
#define OFF_S2 (16ULL*MEG)
#define OFF_W1 (20ULL*MEG)
#define OFF_W2 (84ULL*MEG)
#define WT_TOT (148ULL*MEG)
__device__ __nv_bfloat16 g_wt[WT_TOT];

__device__ __forceinline__ float gelu_exact(float v) {
    return 0.5f * v * (1.0f + erff(v * 0.7071067811865476f));
}
__device__ __forceinline__ uint32_t s2u(const void* p) {
    uint32_t a;
    asm("{ .reg .u64 t; cvta.to.shared.u64 t, %1; cvt.u32.u64 %0, t; }" : "=r"(a) : "l"(p));
    return a;
}
__device__ __forceinline__ uint32_t pk2(__nv_bfloat16 a, __nv_bfloat16 b) {
    return (uint32_t)__bfloat16_as_ushort(a) | ((uint32_t)__bfloat16_as_ushort(b) << 16);
}
__device__ __forceinline__ void mma16816(float* d, const uint32_t* a, const uint32_t* b) {
    asm volatile("mma.sync.aligned.m16n8k16.row.col.f32.bf16.bf16.f32 "
        "{%0,%1,%2,%3}, {%4,%5,%6,%7}, {%8,%9}, {%0,%1,%2,%3};"
        : "+f"(d[0]), "+f"(d[1]), "+f"(d[2]), "+f"(d[3])
        : "r"(a[0]), "r"(a[1]), "r"(a[2]), "r"(a[3]), "r"(b[0]), "r"(b[1]));
}
#define LDSM_X4(r, addr) \
    asm volatile("ldmatrix.sync.aligned.m8n8.x4.shared.b16 {%0,%1,%2,%3}, [%4];" \
        : "=r"((r)[0]), "=r"((r)[1]), "=r"((r)[2]), "=r"((r)[3]) : "r"(addr))
#define LDSM_X4T(r, addr) \
    asm volatile("ldmatrix.sync.aligned.m8n8.x4.trans.shared.b16 {%0,%1,%2,%3}, [%4];" \
        : "=r"((r)[0]), "=r"((r)[1]), "=r"((r)[2]), "=r"((r)[3]) : "r"(addr))
#define CP16(smaddr, gptr) \
    asm volatile("cp.async.ca.shared.global [%0], [%1], 16;" :: "r"(smaddr), "l"(gptr))
#define CP_COMMIT() asm volatile("cp.async.commit_group;" ::: "memory")
#define CP_WAIT0()  asm volatile("cp.async.wait_group 0;" ::: "memory")

// ===== weight transpose + split: W[K,N] -> Wt[s][n][k], 64k x 32n tiles, uint4 stores =====
template<int NS>
__global__ void wtrans_kernel(const float* __restrict__ W, __nv_bfloat16* __restrict__ Wt,
                              int K, int N)
{
    __shared__ float t[64][33];
    const long long wb = (long long)blockIdx.z * K * N;
    __nv_bfloat16* out = Wt + (long long)blockIdx.z * NS * (long long)K * N;
    const long long plane = (long long)K * N;
    const int n0 = blockIdx.x * 32, k0 = blockIdx.y * 64;
    #pragma unroll
    for (int jj = 0; jj < 8; jj++)
        t[threadIdx.y + 8 * jj][threadIdx.x] =
            W[wb + (long long)(k0 + threadIdx.y + 8 * jj) * N + n0 + threadIdx.x];
    __syncthreads();
    const int tid = threadIdx.y * 32 + threadIdx.x;
    const int n_loc = tid >> 3, k8 = (tid & 7) * 8;
    float v[8];
    #pragma unroll
    for (int e = 0; e < 8; e++) v[e] = t[k8 + e][n_loc];
    const long long o = (long long)(n0 + n_loc) * K + k0 + k8;
    #pragma unroll
    for (int s = 0; s < NS; s++) {
        __nv_bfloat16 h[8];
        #pragma unroll
        for (int e = 0; e < 8; e++) {
            h[e] = __float2bfloat16(v[e]);
            if (s + 1 < NS) v[e] -= __bfloat162float(h[e]);
        }
        uint4 pkv;
        pkv.x = pk2(h[0], h[1]); pkv.y = pk2(h[2], h[3]);
        pkv.z = pk2(h[4], h[5]); pkv.w = pk2(h[6], h[7]);
        *(uint4*)(out + s * plane + o) = pkv;
    }
}

// ===== HMMA GEMM: both operands pre-split bf16 planes, full cp.async =====
// OUT: 0 = fp32, 1 = fp32+residual, 2 = gelu + split2 bf16 planes
#define RS 40
#define PLB (128*RS*2)

template<int NS, int OUT>
__global__ __launch_bounds__(256, (NS == 2) ? 2 : 1)
void hmma_gemm_kernel(const __nv_bfloat16* __restrict__ Ap, const __nv_bfloat16* __restrict__ Bt,
                      const float* __restrict__ bias, const float* __restrict__ Rsrc,
                      float* __restrict__ Cf, __nv_bfloat16* __restrict__ Cp,
                      int N, int K,
                      long long planeA, long long sAb, long long sBb, long long sBias,
                      long long sCb, long long planeC)
{
    extern __shared__ __align__(16) char sm[];
    const int tid = threadIdx.x, wid = tid >> 5, lane = tid & 31;
    const int STG = 2 * NS * PLB;

    Ap   += (long long)blockIdx.z * sAb;
    Bt   += (long long)blockIdx.z * sBb;
    bias += (long long)blockIdx.z * sBias;
    if (OUT == 2) Cp += (long long)blockIdx.z * sCb;
    else          Cf += (long long)blockIdx.z * sCb;
    if (OUT == 1) Rsrc += (long long)blockIdx.z * sCb;

    const long long planeB = (long long)N * K;
    const int rowBase = blockIdx.y * 128, colBase = blockIdx.x * 128;
    const uint32_t smb = s2u(sm);

    const int lr = tid >> 1, kh = (tid & 1) * 16;
    const __nv_bfloat16* aRow = Ap + (long long)(rowBase + lr) * K + kh;
    const __nv_bfloat16* bRow = Bt + (long long)(colBase + lr) * K + kh;
    const uint32_t aOff = (uint32_t)(lr * (RS * 2) + kh * 2);
    const uint32_t bOff = (uint32_t)(NS * PLB + lr * (RS * 2) + kh * 2);

    const int wm = (wid & 3) * 32, wn = (wid >> 2) * 64;
    const uint32_t aFragO = (uint32_t)((wm + (lane & 15)) * (RS * 2) + ((lane >> 4) * 8) * 2);
    const uint32_t bFragO = (uint32_t)(NS * PLB
        + (wn + (lane >> 4) * 8 + (lane & 7)) * (RS * 2) + ((lane >> 3) & 1) * 16);

    float acc[2][8][4];
    #pragma unroll
    for (int mi = 0; mi < 2; mi++)
        #pragma unroll
        for (int ni = 0; ni < 8; ni++)
            #pragma unroll
            for (int c = 0; c < 4; c++) acc[mi][ni][c] = 0.f;

    const int nIter = K >> 5;

    #pragma unroll
    for (int s = 0; s < NS; s++) {
        CP16(smb + s * PLB + aOff,      aRow + s * planeA);
        CP16(smb + s * PLB + aOff + 16, aRow + s * planeA + 8);
        CP16(smb + s * PLB + bOff,      bRow + s * planeB);
        CP16(smb + s * PLB + bOff + 16, bRow + s * planeB + 8);
    }
    CP_COMMIT();

    for (int it = 0; it < nIter; ++it) {
        const uint32_t sb = smb + (uint32_t)(it & 1) * STG;
        CP_WAIT0();
        __syncthreads();

        if (it + 1 < nIter) {
            const int kn = (it + 1) << 5;
            const uint32_t sn = smb + (uint32_t)((it + 1) & 1) * STG;
            #pragma unroll
            for (int s = 0; s < NS; s++) {
                CP16(sn + s * PLB + aOff,      aRow + s * planeA + kn);
                CP16(sn + s * PLB + aOff + 16, aRow + s * planeA + kn + 8);
                CP16(sn + s * PLB + bOff,      bRow + s * planeB + kn);
                CP16(sn + s * PLB + bOff + 16, bRow + s * planeB + kn + 8);
            }
            CP_COMMIT();
        }

        #pragma unroll
        for (int kk = 0; kk < 32; kk += 16) {
            uint32_t af[NS][2][4];
            #pragma unroll
            for (int i = 0; i < NS; i++)
                #pragma unroll
                for (int mi = 0; mi < 2; mi++)
                    LDSM_X4(af[i][mi], sb + i * PLB + aFragO + (mi * 16) * (RS * 2) + kk * 2);
            #pragma unroll
            for (int j = 0; j < NS; j++) {
                uint32_t bfr[16];
                #pragma unroll
                for (int p = 0; p < 4; p++)
                    LDSM_X4(bfr + p * 4, sb + j * PLB + bFragO + (p * 16) * (RS * 2) + kk * 2);
                #pragma unroll
                for (int i = 0; i < NS; i++) {
                    if (i + j >= NS) continue;
                    #pragma unroll
                    for (int mi = 0; mi < 2; mi++)
                        #pragma unroll
                        for (int ni = 0; ni < 8; ni++)
                            mma16816(acc[mi][ni], af[i][mi],
                                     bfr + (ni >> 1) * 4 + (ni & 1) * 2);
                }
            }
        }
        __syncthreads();
    }

    #pragma unroll
    for (int mi = 0; mi < 2; mi++) {
        #pragma unroll
        for (int half = 0; half < 2; half++) {
            const int r = rowBase + wm + mi * 16 + (lane >> 2) + half * 8;
            const long long cidx = (long long)r * N + colBase + wn + (lane & 3) * 2;
            const float* bp = bias + colBase + wn + (lane & 3) * 2;
            #pragma unroll
            for (int ni = 0; ni < 8; ni++) {
                float x0 = acc[mi][ni][half * 2 + 0] + bp[ni * 8];
                float x1 = acc[mi][ni][half * 2 + 1] + bp[ni * 8 + 1];
                if (OUT == 2) {
                    x0 = gelu_exact(x0); x1 = gelu_exact(x1);
                    __nv_bfloat16 h0 = __float2bfloat16(x0), h1 = __float2bfloat16(x1);
                    __nv_bfloat16 l0 = __float2bfloat16(x0 - __bfloat162float(h0));
                    __nv_bfloat16 l1 = __float2bfloat16(x1 - __bfloat162float(h1));
                    *(uint32_t*)(Cp + cidx + ni * 8)          = pk2(h0, h1);
                    *(uint32_t*)(Cp + planeC + cidx + ni * 8) = pk2(l0, l1);
                } else {
                    if (OUT == 1) {
                        float2 rr = *(const float2*)(Rsrc + cidx + ni * 8);
                        x0 += rr.x; x1 += rr.y;
                    }
                    float2 o2; o2.x = x0; o2.y = x1;
                    *(float2*)(Cf + cidx + ni * 8) = o2;
                }
            }
        }
    }
}

// ===== HMMA flash attention (fp32 K/V load + in-loop split) =====
#define ARS 72
#define QPL (128*ARS*2)
#define KPL (64*ARS*2)
#define ATTN_SM (3*QPL + 6*KPL)

__global__ __launch_bounds__(256)
void attn_hmma_kernel(const float* __restrict__ Qg, const float* __restrict__ Kg,
                      const float* __restrict__ Vg, const unsigned char* __restrict__ mask,
                      __nv_bfloat16* __restrict__ Op)
{
    extern __shared__ __align__(16) char smr[];
    const int tid = threadIdx.x, wid = tid >> 5, lane = tid & 31;
    const int h = blockIdx.y, b = blockIdx.z;
    const size_t qrow0 = (size_t)b * S_ + blockIdx.x * 128;
    const uint32_t uQ = s2u(smr), uK = uQ + 3 * QPL, uV = uK + 3 * KPL;

    {
        const int r = tid >> 1, c = (tid & 1) * 32;
        const float* src = Qg + (qrow0 + r) * D_ + h * HD_ + c;
        float v[32];
        #pragma unroll
        for (int q = 0; q < 8; q++) *(float4*)(v + q * 4) = *(const float4*)(src + q * 4);
        #pragma unroll
        for (int e = 0; e < 32; e++) v[e] *= 0.125f;
        char* dst = smr + r * (ARS * 2) + c * 2;
        #pragma unroll
        for (int s = 0; s < 3; s++) {
            __nv_bfloat16 hh[32];
            #pragma unroll
            for (int e = 0; e < 32; e++) {
                hh[e] = __float2bfloat16(v[e]);
                if (s < 2) v[e] -= __bfloat162float(hh[e]);
            }
            #pragma unroll
            for (int q = 0; q < 4; q++) {
                uint4 pkv;
                pkv.x = pk2(hh[q*8+0], hh[q*8+1]); pkv.y = pk2(hh[q*8+2], hh[q*8+3]);
                pkv.z = pk2(hh[q*8+4], hh[q*8+5]); pkv.w = pk2(hh[q*8+6], hh[q*8+7]);
                *(uint4*)(dst + s * QPL + q * 16) = pkv;
            }
        }
    }

    float o[8][4];
    #pragma unroll
    for (int nf = 0; nf < 8; nf++)
        #pragma unroll
        for (int c = 0; c < 4; c++) o[nf][c] = 0.f;
    float mrun0 = -1e30f, mrun1 = -1e30f, l0 = 0.f, l1 = 0.f;

    const int kr = tid >> 2, kq = (tid & 3) * 16;
    const int grp = lane >> 3;

    for (int j = 0; j < S_ / 64; j++) {
        __syncthreads();
        {
            const size_t base = (size_t)(b * S_ + j * 64 + kr) * D_ + h * HD_ + kq;
            float kv[16], vv[16];
            #pragma unroll
            for (int q = 0; q < 4; q++) {
                *(float4*)(kv + q * 4) = *(const float4*)(Kg + base + q * 4);
                *(float4*)(vv + q * 4) = *(const float4*)(Vg + base + q * 4);
            }
            char* kd = smr + 3 * QPL + kr * (ARS * 2) + kq * 2;
            char* vd = kd + 3 * KPL;
            #pragma unroll
            for (int s = 0; s < 3; s++) {
                __nv_bfloat16 hk[16], hv[16];
                #pragma unroll
                for (int e = 0; e < 16; e++) {
                    hk[e] = __float2bfloat16(kv[e]);
                    hv[e] = __float2bfloat16(vv[e]);
                    if (s < 2) { kv[e] -= __bfloat162float(hk[e]); vv[e] -= __bfloat162float(hv[e]); }
                }
                uint4 a, bb;
                a.x = pk2(hk[0],hk[1]); a.y = pk2(hk[2],hk[3]); a.z = pk2(hk[4],hk[5]); a.w = pk2(hk[6],hk[7]);
                *(uint4*)(kd + s * KPL) = a;
                a.x = pk2(hk[8],hk[9]); a.y = pk2(hk[10],hk[11]); a.z = pk2(hk[12],hk[13]); a.w = pk2(hk[14],hk[15]);
                *(uint4*)(kd + s * KPL + 16) = a;
                bb.x = pk2(hv[0],hv[1]); bb.y = pk2(hv[2],hv[3]); bb.z = pk2(hv[4],hv[5]); bb.w = pk2(hv[6],hv[7]);
                *(uint4*)(vd + s * KPL) = bb;
                bb.x = pk2(hv[8],hv[9]); bb.y = pk2(hv[10],hv[11]); bb.z = pk2(hv[12],hv[13]); bb.w = pk2(hv[14],hv[15]);
                *(uint4*)(vd + s * KPL + 16) = bb;
            }
        }
        __syncthreads();

        float sacc[8][4];
        #pragma unroll
        for (int nf = 0; nf < 8; nf++)
            #pragma unroll
            for (int c = 0; c < 4; c++) sacc[nf][c] = 0.f;

        #pragma unroll
        for (int jpl = 0; jpl < 3; jpl++) {
            #pragma unroll
            for (int kf = 0; kf < 4; kf++) {
                uint32_t kb[16];
                #pragma unroll
                for (int nfp = 0; nfp < 4; nfp++) {
                    uint32_t addr = uK + jpl * KPL
                        + (uint32_t)((nfp * 16 + (grp >> 1) * 8 + (lane & 7)) * (ARS * 2))
                        + kf * 32 + (grp & 1) * 16;
                    LDSM_X4(kb + nfp * 4, addr);
                }
                #pragma unroll
                for (int ipl = 0; ipl < 3; ipl++) {
                    if (ipl + jpl >= 3) continue;
                    uint32_t aq[4];
                    uint32_t qaddr = uQ + ipl * QPL
                        + (uint32_t)((wid * 16 + (lane & 15)) * (ARS * 2))
                        + kf * 32 + (lane >> 4) * 16;
                    LDSM_X4(aq, qaddr);
                    #pragma unroll
                    for (int nf = 0; nf < 8; nf++)
                        mma16816(sacc[nf], aq, kb + (nf >> 1) * 4 + (nf & 1) * 2);
                }
            }
        }

        const unsigned char* mrow = mask + b * S_ + j * 64;
        #pragma unroll
        for (int nf = 0; nf < 8; nf++) {
            uchar2 mm = *(const uchar2*)(mrow + nf * 8 + (lane & 3) * 2);
            if (mm.x) { sacc[nf][0] = -1e30f; sacc[nf][2] = -1e30f; }
            if (mm.y) { sacc[nf][1] = -1e30f; sacc[nf][3] = -1e30f; }
        }
        float nm0 = mrun0, nm1 = mrun1;
        #pragma unroll
        for (int nf = 0; nf < 8; nf++) {
            nm0 = fmaxf(nm0, fmaxf(sacc[nf][0], sacc[nf][1]));
            nm1 = fmaxf(nm1, fmaxf(sacc[nf][2], sacc[nf][3]));
        }
        nm0 = fmaxf(nm0, __shfl_xor_sync(0xffffffffu, nm0, 1));
        nm0 = fmaxf(nm0, __shfl_xor_sync(0xffffffffu, nm0, 2));
        nm1 = fmaxf(nm1, __shfl_xor_sync(0xffffffffu, nm1, 1));
        nm1 = fmaxf(nm1, __shfl_xor_sync(0xffffffffu, nm1, 2));
        const float al0 = __expf(mrun0 - nm0), al1 = __expf(mrun1 - nm1);
        mrun0 = nm0; mrun1 = nm1;
        float ps0 = 0.f, ps1 = 0.f;
        #pragma unroll
        for (int nf = 0; nf < 8; nf++) {
            sacc[nf][0] = __expf(sacc[nf][0] - nm0); ps0 += sacc[nf][0];
            sacc[nf][1] = __expf(sacc[nf][1] - nm0); ps0 += sacc[nf][1];
            sacc[nf][2] = __expf(sacc[nf][2] - nm1); ps1 += sacc[nf][2];
            sacc[nf][3] = __expf(sacc[nf][3] - nm1); ps1 += sacc[nf][3];
        }
        ps0 += __shfl_xor_sync(0xffffffffu, ps0, 1);
        ps0 += __shfl_xor_sync(0xffffffffu, ps0, 2);
        ps1 += __shfl_xor_sync(0xffffffffu, ps1, 1);
        ps1 += __shfl_xor_sync(0xffffffffu, ps1, 2);
        l0 = l0 * al0 + ps0;
        l1 = l1 * al1 + ps1;
        #pragma unroll
        for (int nf = 0; nf < 8; nf++) {
            o[nf][0] *= al0; o[nf][1] *= al0; o[nf][2] *= al1; o[nf][3] *= al1;
        }

        uint32_t pa[3][4][4];
        #pragma unroll
        for (int kf = 0; kf < 4; kf++) {
            float e[8];
            e[0] = sacc[2*kf][0];   e[1] = sacc[2*kf][1];
            e[2] = sacc[2*kf][2];   e[3] = sacc[2*kf][3];
            e[4] = sacc[2*kf+1][0]; e[5] = sacc[2*kf+1][1];
            e[6] = sacc[2*kf+1][2]; e[7] = sacc[2*kf+1][3];
            #pragma unroll
            for (int pl = 0; pl < 3; pl++) {
                __nv_bfloat16 hh[8];
                #pragma unroll
                for (int q = 0; q < 8; q++) {
                    hh[q] = __float2bfloat16(e[q]);
                    if (pl < 2) e[q] -= __bfloat162float(hh[q]);
                }
                pa[pl][kf][0] = pk2(hh[0], hh[1]);
                pa[pl][kf][1] = pk2(hh[2], hh[3]);
                pa[pl][kf][2] = pk2(hh[4], hh[5]);
                pa[pl][kf][3] = pk2(hh[6], hh[7]);
            }
        }

        #pragma unroll
        for (int vpl = 0; vpl < 3; vpl++) {
            #pragma unroll
            for (int kf = 0; kf < 4; kf++) {
                uint32_t vb[16];
                #pragma unroll
                for (int nfp = 0; nfp < 4; nfp++) {
                    uint32_t addr = uV + vpl * KPL
                        + (uint32_t)((kf * 16 + (grp & 1) * 8 + (lane & 7)) * (ARS * 2))
                        + (2 * nfp + (grp >> 1)) * 16;
                    LDSM_X4T(vb + nfp * 4, addr);
                }
                #pragma unroll
                for (int ppl = 0; ppl < 3; ppl++) {
                    if (ppl + vpl >= 3) continue;
                    #pragma unroll
                    for (int nf = 0; nf < 8; nf++)
                        mma16816(o[nf], pa[ppl][kf], vb + (nf >> 1) * 4 + (nf & 1) * 2);
                }
            }
        }
    }

    const float inv0 = (l0 > 0.f) ? 1.f / l0 : 0.f;
    const float inv1 = (l1 > 0.f) ? 1.f / l1 : 0.f;
    const size_t row0 = qrow0 + wid * 16 + (lane >> 2);
    const size_t idx0 = row0 * D_ + h * HD_ + (lane & 3) * 2;
    const size_t idx1 = idx0 + 8 * D_;
    #pragma unroll
    for (int nf = 0; nf < 8; nf++) {
        float vx = o[nf][0] * inv0, vy = o[nf][1] * inv0;
        float wx = o[nf][2] * inv1, wy = o[nf][3] * inv1;
        #pragma unroll
        for (int pl = 0; pl < 3; pl++) {
            __nv_bfloat16 hx = __float2bfloat16(vx), hy = __float2bfloat16(vy);
            __nv_bfloat16 gx = __float2bfloat16(wx), gy = __float2bfloat16(wy);
            if (pl < 2) {
                vx -= __bfloat162float(hx); vy -= __bfloat162float(hy);
                wx -= __bfloat162float(gx); wy -= __bfloat162float(gy);
            }
            *(uint32_t*)(Op + pl * TD + idx0 + nf * 8) = pk2(hx, hy);
            *(uint32_t*)(Op + pl * TD + idx1 + nf * 8) = pk2(gx, gy);
        }
    }
}

// ===== LayerNorm -> bf16 planes (+ optional fp32) =====
template<int NS, bool F32>
__global__ void ln_kernel(const float* __restrict__ x, const float* __restrict__ g,
                          const float* __restrict__ b, float* __restrict__ outf,
                          __nv_bfloat16* __restrict__ outp)
{
    const int t = blockIdx.x, tid = threadIdx.x;
    const float* xr = x + (size_t)t * D_;
    const int i0 = tid * 4;
    float4 xv = *(const float4*)(xr + i0);
    float s  = xv.x + xv.y + xv.z + xv.w;
    float s2 = xv.x * xv.x + xv.y * xv.y + xv.z * xv.z + xv.w * xv.w;
    __shared__ float sm1[8], sm2[8];
    #pragma unroll
    for (int o = 16; o > 0; o >>= 1) {
        s  += __shfl_down_sync(0xffffffffu, s,  o);
        s2 += __shfl_down_sync(0xffffffffu, s2, o);
    }
    const int wid = tid >> 5, lane = tid & 31;
    if (lane == 0) { sm1[wid] = s; sm2[wid] = s2; }
    __syncthreads();
    if (tid == 0) {
        float a = 0.f, c = 0.f;
        #pragma unroll
        for (int w = 0; w < 8; w++) { a += sm1[w]; c += sm2[w]; }
        sm1[0] = a; sm2[0] = c;
    }
    __syncthreads();
    const float mean = sm1[0] * (1.f / D_);
    const float var  = sm2[0] * (1.f / D_) - mean * mean;
    const float rstd = rsqrtf(var + 1e-5f);
    float4 gv = *(const float4*)(g + i0);
    float4 bv = *(const float4*)(b + i0);
    float y[4];
    y[0] = (xv.x - mean) * rstd * gv.x + bv.x;
    y[1] = (xv.y - mean) * rstd * gv.y + bv.y;
    y[2] = (xv.z - mean) * rstd * gv.z + bv.z;
    y[3] = (xv.w - mean) * rstd * gv.w + bv.w;
    if (F32) *(float4*)(outf + (size_t)t * D_ + i0) = *(float4*)y;
    float v[4] = {y[0], y[1], y[2], y[3]};
    #pragma unroll
    for (int sp = 0; sp < NS; sp++) {
        __nv_bfloat16 h[4];
        #pragma unroll
        for (int e = 0; e < 4; e++) {
            h[e] = __float2bfloat16(v[e]);
            if (sp + 1 < NS) v[e] -= __bfloat162float(h[e]);
        }
        uint2 pkv; pkv.x = pk2(h[0], h[1]); pkv.y = pk2(h[2], h[3]);
        *(uint2*)(outp + (size_t)sp * TD + (size_t)t * D_ + i0) = pkv;
    }
}

// ===== router =====
__global__ void router_kernel(const float* __restrict__ xn, const float* __restrict__ wr,
                              int* __restrict__ eidx, float* __restrict__ gate)
{
    const int t = blockIdx.x;
    float acc[E_];
    #pragma unroll
    for (int e = 0; e < E_; e++) acc[e] = 0.f;
    const float* xr = xn + (size_t)t * D_;
    for (int i = threadIdx.x; i < D_; i += 256) {
        const float xv = xr[i];
        const float* wrow = wr + (size_t)i * E_;
        #pragma unroll
        for (int e = 0; e < E_; e++) acc[e] += xv * wrow[e];
    }
    __shared__ float red[8][E_];
    #pragma unroll
    for (int e = 0; e < E_; e++)
        #pragma unroll
        for (int o = 16; o > 0; o >>= 1)
            acc[e] += __shfl_down_sync(0xffffffffu, acc[e], o);
    const int wid = threadIdx.x >> 5, lane = threadIdx.x & 31;
    if (lane == 0)
        #pragma unroll
        for (int e = 0; e < E_; e++) red[wid][e] = acc[e];
    __syncthreads();
    if (threadIdx.x == 0) {
        float lg[E_];
        #pragma unroll
        for (int e = 0; e < E_; e++) {
            float s = 0.f;
            #pragma unroll
            for (int w = 0; w < 8; w++) s += red[w][e];
            lg[e] = s;
        }
        float m = lg[0];
        #pragma unroll
        for (int e = 1; e < E_; e++) m = fmaxf(m, lg[e]);
        float p[E_], sum = 0.f;
        #pragma unroll
        for (int e = 0; e < E_; e++) { p[e] = expf(lg[e] - m); sum += p[e]; }
        const float invs = 1.f / sum;
        #pragma unroll
        for (int e = 0; e < E_; e++) p[e] *= invs;
        int e0 = 0;
        #pragma unroll
        for (int e = 1; e < E_; e++) if (p[e] > p[e0]) e0 = e;
        int e1 = (e0 == 0) ? 1 : 0;
        #pragma unroll
        for (int e = 0; e < E_; e++) if (e != e0 && p[e] > p[e1]) e1 = e;
        const float v0 = p[e0], v1 = p[e1];
        const float inv = 1.f / (v0 + v1);
        eidx[t]      = e0; gate[t]      = v0 * inv;
        eidx[T_ + t] = e1; gate[T_ + t] = v1 * inv;
    }
}

__global__ void pos_kernel(const int* __restrict__ eidx, int* __restrict__ pos)
{
    const int e = blockIdx.x;
    __shared__ int cnts[256];
    const int base = threadIdx.x * 64;
    int c = 0;
    for (int i = 0; i < 64; i++) c += (eidx[base + i] == e) ? 1 : 0;
    cnts[threadIdx.x] = c;
    __syncthreads();
    if (threadIdx.x == 0) {
        int run = 0;
        for (int k = 0; k < 256; k++) { int v = cnts[k]; cnts[k] = run; run += v; }
    }
    __syncthreads();
    int run = cnts[threadIdx.x];
    for (int i = 0; i < 64; i++)
        if (eidx[base + i] == e) pos[base + i] = run++;
}

__global__ void scatter_kernel(const __nv_bfloat16* __restrict__ xp, const int* __restrict__ eidx,
                               const int* __restrict__ pos, __nv_bfloat16* __restrict__ dp)
{
    const int i = blockIdx.x;
    const int p = pos[i];
    if (p >= CAP_) return;
    const int e = eidx[i];
    const int t = i & (T_ - 1);
    const size_t PL = (size_t)E_ * CAP_ * D_;
    #pragma unroll
    for (int pl = 0; pl < 2; pl++) {
        const uint2* src = (const uint2*)(xp + (size_t)pl * TD + (size_t)t * D_);
        uint2* dst = (uint2*)(dp + pl * PL + ((size_t)e * CAP_ + p) * D_);
        dst[threadIdx.x] = src[threadIdx.x];
    }
}

__global__ void combine_kernel(const float* __restrict__ x1, const float* __restrict__ sh2,
                               const float* __restrict__ eo, const int* __restrict__ eidx,
                               const int* __restrict__ pos, const float* __restrict__ gate,
                               float* __restrict__ out)
{
    const int t = blockIdx.x;
    const int i0 = t, i1 = T_ + t;
    const int p0 = pos[i0], p1 = pos[i1];
    const float w0 = (p0 < CAP_) ? gate[i0] : 0.f;
    const float w1 = (p1 < CAP_) ? gate[i1] : 0.f;
    const float* e0p = eo + ((size_t)eidx[i0] * CAP_ + min(p0, CAP_ - 1)) * D_;
    const float* e1p = eo + ((size_t)eidx[i1] * CAP_ + min(p1, CAP_ - 1)) * D_;
    const size_t off = (size_t)t * D_;
    for (int d = threadIdx.x; d < D_; d += 256)
        out[off + d] = x1[off + d] + sh2[off + d] + w0 * e0p[d] + w1 * e1p[d];
}

// ===== host =====
template<int NS, int OUT>
static void hgemm(cudaStream_t st,
                  const __nv_bfloat16* Ap, const __nv_bfloat16* Bt, const float* bias,
                  const float* R, float* Cf, __nv_bfloat16* Cp,
                  int M, int N, int K, int batch,
                  long long planeA, long long sAb, long long sBb, long long sBias,
                  long long sCb, long long planeC)
{
    const int smem = 4 * NS * PLB;
    static bool init[2][3] = {};
    if (!init[NS - 2][OUT]) {
        cudaFuncSetAttribute(hmma_gemm_kernel<NS, OUT>,
                             cudaFuncAttributeMaxDynamicSharedMemorySize, smem);
        init[NS - 2][OUT] = true;
    }
    dim3 grid(N / 128, M / 128, batch);
    hmma_gemm_kernel<NS, OUT><<<grid, 256, smem, st>>>(Ap, Bt, bias, R, Cf, Cp, N, K,
                                                       planeA, sAb, sBb, sBias, sCb, planeC);
}

extern "C" void kernel_launch(void* const* d_in, const int* in_sizes, int n_in,
                              void* d_out, int out_size)
{
    const float* x      = (const float*)d_in[0];
    const unsigned char* mask = (const unsigned char*)d_in[1];
    const float* ln1_g  = (const float*)d_in[2];
    const float* ln1_b  = (const float*)d_in[3];
    const float* wq     = (const float*)d_in[4];
    const float* bq     = (const float*)d_in[5];
    const float* wk     = (const float*)d_in[6];
    const float* bk     = (const float*)d_in[7];
    const float* wv     = (const float*)d_in[8];
    const float* bv     = (const float*)d_in[9];
    const float* wo     = (const float*)d_in[10];
    const float* bo     = (const float*)d_in[11];
    const float* ln2_g  = (const float*)d_in[12];
    const float* ln2_b  = (const float*)d_in[13];
    const float* wrout  = (const float*)d_in[14];
    const float* w1     = (const float*)d_in[15];
    const float* b1     = (const float*)d_in[16];
    const float* w2     = (const float*)d_in[17];
    const float* b2     = (const float*)d_in[18];
    const float* ws1    = (const float*)d_in[19];
    const float* bs1    = (const float*)d_in[20];
    const float* ws2    = (const float*)d_in[21];
    const float* bs2    = (const float*)d_in[22];
    float* out = (float*)d_out;

    float *qkv, *x1, *xn2, *sh2, *eo, *gate, *bqkv;
    int *eidx, *pos;
    __nv_bfloat16 *wt, *xn1p, *attnp, *xn2p, *dispp, *hbufp, *sh1p;
    cudaGetSymbolAddress((void**)&qkv,   g_qkv);
    cudaGetSymbolAddress((void**)&x1,    g_x1);
    cudaGetSymbolAddress((void**)&xn2,   g_xn2);
    cudaGetSymbolAddress((void**)&sh2,   g_sh2);
    cudaGetSymbolAddress((void**)&eo,    g_eo);
    cudaGetSymbolAddress((void**)&gate,  g_gate);
    cudaGetSymbolAddress((void**)&bqkv,  g_bqkv);
    cudaGetSymbolAddress((void**)&eidx,  g_eidx);
    cudaGetSymbolAddress((void**)&pos,   g_pos);
    cudaGetSymbolAddress((void**)&wt,    g_wt);
    cudaGetSymbolAddress((void**)&xn1p,  g_xn1p);
    cudaGetSymbolAddress((void**)&attnp, g_attnp);
    cudaGetSymbolAddress((void**)&xn2p,  g_xn2p);
    cudaGetSymbolAddress((void**)&dispp, g_dispp);
    cudaGetSymbolAddress((void**)&hbufp, g_hbufp);
    cudaGetSymbolAddress((void**)&sh1p,  g_sh1p);

    static bool ainit = false;
    static cudaStream_t st2 = nullptr;
    static cudaEvent_t evFork, evWt, evXn2, evShared;
    if (!ainit) {
        cudaFuncSetAttribute(attn_hmma_kernel, cudaFuncAttributeMaxDynamicSharedMemorySize, ATTN_SM);
        cudaStreamCreateWithFlags(&st2, cudaStreamNonBlocking);
        cudaEventCreateWithFlags(&evFork,   cudaEventDisableTiming);
        cudaEventCreateWithFlags(&evWt,     cudaEventDisableTiming);
        cudaEventCreateWithFlags(&evXn2,    cudaEventDisableTiming);
        cudaEventCreateWithFlags(&evShared, cudaEventDisableTiming);
        ainit = true;
    }

    cudaMemcpyAsync(bqkv,          bq, D_ * sizeof(float), cudaMemcpyDeviceToDevice, 0);
    cudaMemcpyAsync(bqkv + D_,     bk, D_ * sizeof(float), cudaMemcpyDeviceToDevice, 0);
    cudaMemcpyAsync(bqkv + 2 * D_, bv, D_ * sizeof(float), cudaMemcpyDeviceToDevice, 0);

    dim3 tb(32, 8);
    // fork: big weight transposes on stream 2 (overlap with attention path)
    cudaEventRecord(evFork, 0);
    cudaStreamWaitEvent(st2, evFork, 0);
    wtrans_kernel<2><<<dim3(64, 16, 1), tb, 0, st2>>>(ws1, wt + OFF_S1, D_, FS_);
    wtrans_kernel<2><<<dim3(32, 32, 1), tb, 0, st2>>>(ws2, wt + OFF_S2, FS_, D_);
    wtrans_kernel<2><<<dim3(128, 16, 8), tb, 0, st2>>>(w1, wt + OFF_W1, D_, F_);
    wtrans_kernel<2><<<dim3(32, 64, 8), tb, 0, st2>>>(w2, wt + OFF_W2, F_, D_);
    cudaEventRecord(evWt, st2);

    // stream 0: attention-path transposes + attention block
    wtrans_kernel<3><<<dim3(32, 16, 1), tb>>>(wq,  wt + OFF_Q,  D_, D_);
    wtrans_kernel<3><<<dim3(32, 16, 1), tb>>>(wk,  wt + OFF_Kw, D_, D_);
    wtrans_kernel<3><<<dim3(32, 16, 1), tb>>>(wv,  wt + OFF_V,  D_, D_);
    wtrans_kernel<3><<<dim3(32, 16, 1), tb>>>(wo,  wt + OFF_O,  D_, D_);

    ln_kernel<3, false><<<T_, 256>>>(x, ln1_g, ln1_b, nullptr, xn1p);
    hgemm<3, 0>(0, xn1p, wt + OFF_Q, bqkv, nullptr, qkv, nullptr,
                T_, D_, D_, 3, TD, 0, 3LL * MEG, D_, TD, 0);
    attn_hmma_kernel<<<dim3(S_ / 128, H_, B_), 256, ATTN_SM>>>(
        qkv, qkv + TD, qkv + 2 * TD, mask, attnp);
    hgemm<3, 1>(0, attnp, wt + OFF_O, bo, x, x1, nullptr,
                T_, D_, D_, 1, TD, 0, 0, 0, 0, 0);

    // ---- MoE block ----
    ln_kernel<2, true><<<T_, 256>>>(x1, ln2_g, ln2_b, xn2, xn2p);
    cudaEventRecord(evXn2, 0);

    // shared expert on stream 2 (needs xn2p + ws transposes; overlaps MoE path)
    cudaStreamWaitEvent(st2, evXn2, 0);
    hgemm<2, 2>(st2, xn2p, wt + OFF_S1, bs1, nullptr, nullptr, sh1p,
                T_, FS_, D_, 1, TD, 0, 0, 0, 0, (long long)T_ * FS_);
    hgemm<2, 0>(st2, sh1p, wt + OFF_S2, bs2, nullptr, sh2, nullptr,
                T_, D_, FS_, 1, (long long)T_ * FS_, 0, 0, 0, 0, 0);
    cudaEventRecord(evShared, st2);

    // MoE expert path on stream 0
    router_kernel<<<T_, 256>>>(xn2, wrout, eidx, gate);
    pos_kernel<<<E_, 256>>>(eidx, pos);
    scatter_kernel<<<NKT, 256>>>(xn2p, eidx, pos, dispp);
    cudaStreamWaitEvent(0, evWt, 0);   // w1/w2 transposes done
    hgemm<2, 2>(0, dispp, wt + OFF_W1, b1, nullptr, nullptr, hbufp,
                CAP_, F_, D_, E_,
                (long long)E_ * CAP_ * D_, (long long)CAP_ * D_, 2LL * D_ * F_, F_,
                (long long)CAP_ * F_, (long long)E_ * CAP_ * F_);
    hgemm<2, 0>(0, hbufp, wt + OFF_W2, b2, nullptr, eo, nullptr,
                CAP_, D_, F_, E_,
                (long long)E_ * CAP_ * F_, (long long)CAP_ * F_, 2LL * F_ * D_, D_,
                (long long)CAP_ * D_, 0);

    // join shared expert, combine
    cudaStreamWaitEvent(0, evShared, 0);
    combine_kernel<<<T_, 256>>>(x1, sh2, eo, eidx, pos, gate, out);
}